// round 12
// baseline (speedup 1.0000x reference)
#include <cuda_runtime.h>
#include <cuda_bf16.h>
#include <math.h>
#include <stdint.h>

#define BB 8
#define SS 2000
#define MM (BB*SS)          // 16000 rows
#define DD 256
#define HH 2
#define HDIM 128
#define FFN 256
#define WIN 99
#define KK 256              // all GEMMs have K=256
#define QSCALE 0.08838834764831845f

// ---------------- scratch (device globals; no allocation allowed) ----------
__device__ float g_x   [MM*DD];    // encoder out + pos (rounded)
__device__ float g_ctx [MM*DD];    // attention context (rounded)
__device__ float g_att [MM*DD];    // out_proj output (full fp32)
__device__ float g_h1  [MM*DD];    // after LN1 (rounded)
__device__ float g_ff  [MM*FFN];   // relu(ffn1) (rounded)
__device__ float g_ff2 [MM*DD];    // ffn2 (full fp32)
__device__ float g_wc  [260];      // fused head weights + bias
__device__ float g_pos [SS*DD];    // positional encoding table

// bf16 hi/lo q/k/v emitted by qkv GEMM epilogue
// q,k: [bh][s][128]; vT: [bh][d][s]
#define QKN (16*2000*128)
__device__ __nv_bfloat16 g_qh[QKN], g_ql[QKN];
__device__ __nv_bfloat16 g_kh[QKN], g_kl[QKN];
__device__ __nv_bfloat16 g_vth[QKN], g_vtl[QKN];

// tf32-rounded weights, packed: enc | qkv | outproj | lin1 | lin2 (all [N,256])
#define WOFF_ENC 0
#define WOFF_QKV 65536
#define WOFF_OUT 262144
#define WOFF_L1  327680
#define WOFF_L2  393216
#define WTOTAL   458752
__device__ float g_w[WTOTAL];

// ======================= PTX helpers ========================================
__device__ __forceinline__ uint32_t smem_u32(const void* p) {
    uint32_t a;
    asm("{ .reg .u64 t; cvta.to.shared.u64 t, %1; cvt.u32.u64 %0, t; }"
        : "=r"(a) : "l"(p));
    return a;
}

__device__ __forceinline__ float tf32r(float x) {
    uint32_t u;
    asm("cvt.rna.tf32.f32 %0, %1;" : "=r"(u) : "f"(x));
    return __uint_as_float(u);
}

__device__ __forceinline__ uint32_t tf32u(uint32_t x) {
    uint32_t u;
    asm("cvt.rna.tf32.f32 %0, %1;" : "=r"(u) : "f"(__uint_as_float(x)));
    return u;
}

__device__ __forceinline__ void mma_tf32(float* c, const uint32_t* a,
                                         const uint32_t* b) {
    asm volatile(
        "mma.sync.aligned.m16n8k8.row.col.f32.tf32.tf32.f32 "
        "{%0,%1,%2,%3}, {%4,%5,%6,%7}, {%8,%9}, {%0,%1,%2,%3};\n"
        : "+f"(c[0]), "+f"(c[1]), "+f"(c[2]), "+f"(c[3])
        : "r"(a[0]), "r"(a[1]), "r"(a[2]), "r"(a[3]), "r"(b[0]), "r"(b[1]));
}

__device__ __forceinline__ void mma_bf16(float* c, const uint32_t* a,
                                         const uint32_t* b) {
    asm volatile(
        "mma.sync.aligned.m16n8k16.row.col.f32.bf16.bf16.f32 "
        "{%0,%1,%2,%3}, {%4,%5,%6,%7}, {%8,%9}, {%0,%1,%2,%3};\n"
        : "+f"(c[0]), "+f"(c[1]), "+f"(c[2]), "+f"(c[3])
        : "r"(a[0]), "r"(a[1]), "r"(a[2]), "r"(a[3]), "r"(b[0]), "r"(b[1]));
}

__device__ __forceinline__ void ldsm_x4(uint32_t* r, uint32_t addr) {
    asm volatile("ldmatrix.sync.aligned.m8n8.x4.shared.b16 {%0,%1,%2,%3}, [%4];"
        : "=r"(r[0]), "=r"(r[1]), "=r"(r[2]), "=r"(r[3]) : "r"(addr));
}

#define CPASYNC(dst, src) \
    asm volatile("cp.async.cg.shared.global [%0], [%1], 16;" :: "r"(dst), "l"(src))
#define CPCOMMIT() asm volatile("cp.async.commit_group;" ::: "memory")
#define CPWAIT1()  asm volatile("cp.async.wait_group 1;" ::: "memory")
#define CPWAIT0()  asm volatile("cp.async.wait_group 0;" ::: "memory")

__device__ __forceinline__ void split2(float a, float b, uint32_t& hi, uint32_t& lo) {
    __nv_bfloat16 ha = __float2bfloat16(a), hb = __float2bfloat16(b);
    __nv_bfloat16 la = __float2bfloat16(a - __bfloat162float(ha));
    __nv_bfloat16 lb = __float2bfloat16(b - __bfloat162float(hb));
    hi = ((uint32_t)(*(uint16_t*)&hb) << 16) | (uint32_t)(*(uint16_t*)&ha);
    lo = ((uint32_t)(*(uint16_t*)&lb) << 16) | (uint32_t)(*(uint16_t*)&la);
}

// ======================= tf32 single-pass GEMM =============================
// (unchanged from round 10/11 — validated)
#define PITCHB 144          // 36 floats
#define TSA 0
#define TSB 18432
#define TSTAGE 36864
#define TSM_TOTAL (2*TSTAGE)

template<int EPI>
__global__ void __launch_bounds__(256, 2)
tf32_gemm(const float* __restrict__ A, const float* __restrict__ B,
          const float* __restrict__ bias, const float* __restrict__ pos,
          float* __restrict__ outF, int Ntot,
          __nv_bfloat16* __restrict__ qh, __nv_bfloat16* __restrict__ ql,
          __nv_bfloat16* __restrict__ kh, __nv_bfloat16* __restrict__ kl,
          __nv_bfloat16* __restrict__ vth, __nv_bfloat16* __restrict__ vtl)
{
    extern __shared__ char smem[];
    const uint32_t sb = smem_u32(smem);
    const int tid  = threadIdx.x;
    const int wid  = tid >> 5;
    const int lane = tid & 31;
    const int g    = lane >> 2;
    const int t4   = lane & 3;
    const int mi   = lane >> 3;
    const int lr   = lane & 7;
    const int wm   = wid & 3;
    const int wn   = wid >> 2;
    const int row0 = blockIdx.x * 128;
    const int col0 = blockIdx.y * 128;

    float acc[2][8][4];
#pragma unroll
    for (int i = 0; i < 2; i++)
#pragma unroll
        for (int j = 0; j < 8; j++)
#pragma unroll
            for (int k = 0; k < 4; k++) acc[i][j][k] = 0.f;

    auto issue = [&](int st) {
        const int k0 = st * 32;
        const uint32_t base = sb + (st & 1) * TSTAGE;
#pragma unroll
        for (int z = 0; z < 4; z++) {
            const int idx = tid + z * 256;
            const int r = idx >> 3, c = idx & 7;
            CPASYNC(base + TSA + r * PITCHB + c * 16,
                    A + (size_t)(row0 + r) * KK + k0 + c * 4);
        }
#pragma unroll
        for (int z = 0; z < 4; z++) {
            const int idx = tid + z * 256;
            const int r = idx >> 3, c = idx & 7;
            CPASYNC(base + TSB + r * PITCHB + c * 16,
                    B + (size_t)(col0 + r) * KK + k0 + c * 4);
        }
    };

    issue(0); CPCOMMIT();

#pragma unroll 1
    for (int st = 0; st < 8; st++) {
        if (st < 7) { issue(st + 1); CPCOMMIT(); CPWAIT1(); }
        else        { CPWAIT0(); }
        __syncthreads();

        const uint32_t base = sb + (st & 1) * TSTAGE;
#pragma unroll
        for (int s = 0; s < 4; s++) {
            uint32_t af[2][4];
#pragma unroll
            for (int mt = 0; mt < 2; mt++) {
                const uint32_t arow = (uint32_t)(wm * 32 + mt * 16 + (mi & 1) * 8 + lr);
                ldsm_x4(af[mt], base + TSA + arow * PITCHB + s * 32 + (mi >> 1) * 16);
                if (EPI == 1) {
#pragma unroll
                    for (int q = 0; q < 4; q++) af[mt][q] = tf32u(af[mt][q]);
                }
            }
            uint32_t bf[4][4];
#pragma unroll
            for (int nt2 = 0; nt2 < 4; nt2++) {
                const uint32_t brow = (uint32_t)(wn * 64 + nt2 * 16 + (mi & 1) * 8 + lr);
                ldsm_x4(bf[nt2], base + TSB + brow * PITCHB + s * 32 + (mi >> 1) * 16);
            }
#pragma unroll
            for (int mt = 0; mt < 2; mt++)
#pragma unroll
                for (int nt = 0; nt < 8; nt++) {
                    uint32_t bb[2] = { bf[nt >> 1][nt & 1], bf[nt >> 1][(nt & 1) + 2] };
                    mma_tf32(acc[mt][nt], af[mt], bb);
                }
        }
        __syncthreads();
    }

    // ---- epilogue ----
#pragma unroll
    for (int mt = 0; mt < 2; mt++) {
#pragma unroll
        for (int nt = 0; nt < 8; nt++) {
            const int c = col0 + wn * 64 + nt * 8 + t4 * 2;
            const float b0 = bias[c], b1 = bias[c + 1];
#pragma unroll
            for (int half = 0; half < 2; half++) {
                const int r = row0 + wm * 32 + mt * 16 + g + half * 8;
                float v0 = acc[mt][nt][half * 2 + 0] + b0;
                float v1 = acc[mt][nt][half * 2 + 1] + b1;
                if (EPI == 2) { v0 = fmaxf(v0, 0.f); v1 = fmaxf(v1, 0.f); }
                if (EPI == 1) {
                    const int s = r % SS;
                    v0 += pos[s * DD + c];
                    v1 += pos[s * DD + c + 1];
                }
                if (EPI == 3) {
                    const int region = c >> 8;         // 0 q, 1 k, 2 v
                    const int hh = (c >> 7) & 1;
                    const int dloc = c & 127;
                    const int bb2 = r / SS;
                    const int s = r - bb2 * SS;
                    const int bh = bb2 * 2 + hh;
                    if (region == 0) { v0 *= QSCALE; v1 *= QSCALE; }
                    if (region <= 1) {
                        uint32_t hp, lp;
                        split2(v0, v1, hp, lp);
                        const size_t o = ((size_t)(bh * 2000 + s)) * 128 + dloc;
                        __nv_bfloat16* H = region ? kh : qh;
                        __nv_bfloat16* L = region ? kl : ql;
                        *(uint32_t*)(H + o) = hp;
                        *(uint32_t*)(L + o) = lp;
                    } else {
                        const __nv_bfloat16 h0 = __float2bfloat16(v0);
                        const __nv_bfloat16 l0 = __float2bfloat16(v0 - __bfloat162float(h0));
                        const __nv_bfloat16 h1 = __float2bfloat16(v1);
                        const __nv_bfloat16 l1 = __float2bfloat16(v1 - __bfloat162float(h1));
                        const size_t o = ((size_t)(bh * 128 + dloc)) * 2000 + s;
                        vth[o] = h0;        vtl[o] = l0;
                        vth[o + 2000] = h1; vtl[o + 2000] = l1;
                    }
                } else {
                    const size_t o = (size_t)r * Ntot + c;
                    if (EPI == 0) *(float2*)(outF + o) = make_float2(v0, v1);
                    else *(float2*)(outF + o) = make_float2(tf32r(v0), tf32r(v1));
                }
            }
        }
    }
}

// ======================= prep kernels ======================================
#define PN1 WTOTAL
#define PN3 (SS*DD)
__global__ void prep_all_kernel(const float* __restrict__ enc,
                                const float* __restrict__ qkvw,
                                const float* __restrict__ outw,
                                const float* __restrict__ l1,
                                const float* __restrict__ l2,
                                float* __restrict__ wdst,
                                float* __restrict__ pdst)
{
    const int i = blockIdx.x * blockDim.x + threadIdx.x;
    if (i < PN1) {
        float v;
        if      (i < WOFF_QKV) v = enc [i];
        else if (i < WOFF_OUT) v = qkvw[i - WOFF_QKV];
        else if (i < WOFF_L1)  v = outw[i - WOFF_OUT];
        else if (i < WOFF_L2)  v = l1  [i - WOFF_L1];
        else                   v = l2  [i - WOFF_L2];
        wdst[i] = tf32r(v);
    } else if (i < PN1 + PN3) {
        const int j = i - PN1;
        const int s = j / DD;
        const int d = j % DD;
        const int p = d >> 1;
        const float div = expf(-(float)(2 * p) * 0.03597789207803197f);
        const float ang = (float)s * div;
        pdst[j] = (d & 1) ? cosf(ang) : sinf(ang);
    }
}

// head prep: wc[d] = sum_j fc2[j]*fc1[j][d]; parallel over j.
__global__ void head_prep_kernel(const float* __restrict__ fc1_w,
                                 const float* __restrict__ fc1_b,
                                 const float* __restrict__ fc2_w,
                                 const float* __restrict__ fc2_b,
                                 float* __restrict__ wc)
{
    __shared__ float sp[16][16];
    const int t  = threadIdx.x;
    const int dl = t & 15;
    const int jg = t >> 4;
    const int d  = blockIdx.x * 16 + dl;
    float s = 0.f;
#pragma unroll
    for (int j = jg * 4; j < jg * 4 + 4; j++)
        s += fc2_w[j] * fc1_w[j * DD + d];
    sp[jg][dl] = s;
    __syncthreads();
    if (t < 16) {
        float tot = 0.f;
#pragma unroll
        for (int j = 0; j < 16; j++) tot += sp[j][t];
        wc[blockIdx.x * 16 + t] = tot;
    }
    if (blockIdx.x == 0 && t == 0) {
        float bb = fc2_b[0];
        for (int j = 0; j < 64; j++) bb += fc2_w[j] * fc1_b[j];
        wc[256] = bb;
    }
}

// ======================= flash-style banded attention (bf16-in) =============
// Block: one bh x 128 queries, 8 warps (16 rows each). 4 key tiles of 64,
// starting at ks2 = i0-104. K/V double-buffered: tile tt+1 prefetched during
// compute of tile tt (cp.async groups; wait_group 1 in-loop).
// Per-warp valid jj window: [max(w*16+5, 104-i0), w*16+119]; fully-masked
// 16-key blocks skipped in QK and PV.
#define FQH 0
#define FQL 34816
#define FKB 69632            // 2 K buffers, 34816 each (hi 17408 + lo 17408)
#define FVB 139264           // 2 V buffers, 36864 each (hi 18432 + lo 18432)
#define FSM_TOTAL 212992

__global__ void __launch_bounds__(256)
flash_attn_kernel(const __nv_bfloat16* __restrict__ qh, const __nv_bfloat16* __restrict__ ql,
                  const __nv_bfloat16* __restrict__ kh, const __nv_bfloat16* __restrict__ kl,
                  const __nv_bfloat16* __restrict__ vth, const __nv_bfloat16* __restrict__ vtl,
                  float* __restrict__ ctxp)
{
    extern __shared__ char sm[];
    const uint32_t sb = smem_u32(sm);
    const int tid  = threadIdx.x;
    const int w    = tid >> 5;       // 0..7
    const int lane = tid & 31;
    const int g    = lane >> 2;
    const int t4   = lane & 3;
    const int mi   = lane >> 3;
    const int lr   = lane & 7;

    const int i0 = blockIdx.x * 128;
    const int bh = blockIdx.y;
    const int b  = bh >> 1;
    const int h  = bh & 1;
    const int ks2 = i0 - 104;
    const size_t qkbase = (size_t)bh * 2000 * 128;
    const size_t vbase  = (size_t)bh * 128 * 2000;

    // ---- issue K/V tile loads into buffer tt&1 ----
    auto issue_kv = [&](int tt) {
        const int buf = tt & 1;
        const uint32_t kb = sb + FKB + buf * 34816;
        const uint32_t vb = sb + FVB + buf * 36864;
#pragma unroll
        for (int z = 0; z < 4; z++) {
            const int idx = z * 256 + tid;
            const int r = idx >> 4, ch = idx & 15;
            const int j = min(max(ks2 + tt * 64 + r, 0), SS - 1);
            const size_t go = qkbase + (size_t)j * 128 + ch * 8;
            const uint32_t so = (uint32_t)r * 272 + ch * 16;
            CPASYNC(kb + so, kh + go);
            CPASYNC(kb + 17408 + so, kl + go);
        }
#pragma unroll
        for (int z = 0; z < 4; z++) {
            const int idx = z * 256 + tid;
            const int r = idx >> 3, ch = idx & 7;
            const int sc = max(0, min(ks2 + tt * 64 + ch * 8, SS - 8));
            const size_t go = vbase + (size_t)r * 2000 + sc;
            const uint32_t so = (uint32_t)r * 144 + ch * 16;
            CPASYNC(vb + so, vth + go);
            CPASYNC(vb + 18432 + so, vtl + go);
        }
    };

    // ---- Q loads (128 rows) + K/V tile 0 -> group G0 ----
#pragma unroll
    for (int z = 0; z < 8; z++) {
        const int idx = z * 256 + tid;
        const int r = idx >> 4, ch = idx & 15;
        const int row = min(i0 + r, SS - 1);
        const size_t go = qkbase + (size_t)row * 128 + ch * 8;
        const uint32_t so = (uint32_t)r * 272 + ch * 16;
        CPASYNC(sb + FQH + so, qh + go);
        CPASYNC(sb + FQL + so, ql + go);
    }
    issue_kv(0);
    CPCOMMIT();

    float ctx[16][4];
#pragma unroll
    for (int i = 0; i < 16; i++)
#pragma unroll
        for (int j = 0; j < 4; j++) ctx[i][j] = 0.f;

    const int qi0 = w * 16 + g;
    const int qi1 = qi0 + 8;
    const int vlo0 = max(qi0 + 5, 104 - i0), vhi0 = qi0 + 104;
    const int vlo1 = max(qi1 + 5, 104 - i0), vhi1 = qi1 + 104;
    const int wlo = max(w * 16 + 5, 104 - i0);
    const int whi = w * 16 + 119;
    float m0 = -1e30f, m1 = -1e30f, L0 = 0.f, L1 = 0.f;

#pragma unroll 1
    for (int tt = 0; tt < 4; tt++) {
        __syncthreads();             // compute of tile tt-1 done (buffer reuse)
        if (tt < 3) { issue_kv(tt + 1); CPCOMMIT(); CPWAIT1(); }
        else        { CPWAIT0(); }
        __syncthreads();             // tile tt data visible to all warps

        const uint32_t kbh = sb + FKB + (tt & 1) * 34816;
        const uint32_t kbl = kbh + 17408;
        const uint32_t vbh = sb + FVB + (tt & 1) * 36864;
        const uint32_t vbl = vbh + 18432;

        // ---- QK (skip fully-masked 16-key blocks per warp) ----
        float S[8][4];
#pragma unroll
        for (int i = 0; i < 8; i++)
#pragma unroll
            for (int j = 0; j < 4; j++) S[i][j] = 0.f;

#pragma unroll
        for (int kb = 0; kb < 8; kb++) {
            uint32_t aqh[4], aql[4];
            const uint32_t arow = (uint32_t)(w * 16 + (mi & 1) * 8 + lr) * 272
                                + (uint32_t)(kb * 16 + (mi >> 1) * 8) * 2;
            ldsm_x4(aqh, sb + FQH + arow);
            ldsm_x4(aql, sb + FQL + arow);
#pragma unroll
            for (int nbp = 0; nbp < 4; nbp++) {
                const int kblk = tt * 64 + nbp * 16;
                if (kblk + 15 < wlo || kblk > whi) continue;
                uint32_t bkh[4], bkl[4];
                const uint32_t brow = (uint32_t)(nbp * 16 + (mi >> 1) * 8 + lr) * 272
                                    + (uint32_t)(kb * 16 + (mi & 1) * 8) * 2;
                ldsm_x4(bkh, kbh + brow);
                ldsm_x4(bkl, kbl + brow);
                mma_bf16(S[nbp * 2],     aqh, &bkh[0]);
                mma_bf16(S[nbp * 2 + 1], aqh, &bkh[2]);
                mma_bf16(S[nbp * 2],     aqh, &bkl[0]);
                mma_bf16(S[nbp * 2 + 1], aqh, &bkl[2]);
                mma_bf16(S[nbp * 2],     aql, &bkh[0]);
                mma_bf16(S[nbp * 2 + 1], aql, &bkh[2]);
            }
        }

        // ---- band mask + running softmax ----
        float mx0 = -1e30f, mx1 = -1e30f;
#pragma unroll
        for (int nb = 0; nb < 8; nb++) {
            const int jj = tt * 64 + nb * 8 + t4 * 2;
            if (jj < vlo0     || jj > vhi0)     S[nb][0] = -1e30f;
            if (jj + 1 < vlo0 || jj + 1 > vhi0) S[nb][1] = -1e30f;
            if (jj < vlo1     || jj > vhi1)     S[nb][2] = -1e30f;
            if (jj + 1 < vlo1 || jj + 1 > vhi1) S[nb][3] = -1e30f;
            mx0 = fmaxf(mx0, fmaxf(S[nb][0], S[nb][1]));
            mx1 = fmaxf(mx1, fmaxf(S[nb][2], S[nb][3]));
        }
        mx0 = fmaxf(mx0, __shfl_xor_sync(0xffffffffu, mx0, 1));
        mx0 = fmaxf(mx0, __shfl_xor_sync(0xffffffffu, mx0, 2));
        mx1 = fmaxf(mx1, __shfl_xor_sync(0xffffffffu, mx1, 1));
        mx1 = fmaxf(mx1, __shfl_xor_sync(0xffffffffu, mx1, 2));

        const float mn0 = fmaxf(m0, mx0);
        const float mn1 = fmaxf(m1, mx1);
        const float f0 = __expf(m0 - mn0);
        const float f1 = __expf(m1 - mn1);

        float sum0 = 0.f, sum1 = 0.f;
#pragma unroll
        for (int nb = 0; nb < 8; nb++) {
            float e0 = (S[nb][0] == -1e30f) ? 0.f : __expf(S[nb][0] - mn0);
            float e1 = (S[nb][1] == -1e30f) ? 0.f : __expf(S[nb][1] - mn0);
            float e2 = (S[nb][2] == -1e30f) ? 0.f : __expf(S[nb][2] - mn1);
            float e3 = (S[nb][3] == -1e30f) ? 0.f : __expf(S[nb][3] - mn1);
            S[nb][0] = e0; S[nb][1] = e1; S[nb][2] = e2; S[nb][3] = e3;
            sum0 += e0 + e1;
            sum1 += e2 + e3;
        }
        sum0 += __shfl_xor_sync(0xffffffffu, sum0, 1);
        sum0 += __shfl_xor_sync(0xffffffffu, sum0, 2);
        sum1 += __shfl_xor_sync(0xffffffffu, sum1, 1);
        sum1 += __shfl_xor_sync(0xffffffffu, sum1, 2);
        L0 = L0 * f0 + sum0;
        L1 = L1 * f1 + sum1;
        m0 = mn0; m1 = mn1;

#pragma unroll
        for (int nb = 0; nb < 16; nb++) {
            ctx[nb][0] *= f0; ctx[nb][1] *= f0;
            ctx[nb][2] *= f1; ctx[nb][3] *= f1;
        }

        // ---- PV (skip fully-masked 16-key blocks per warp) ----
#pragma unroll
        for (int kb2 = 0; kb2 < 4; kb2++) {
            const int kblk = tt * 64 + kb2 * 16;
            if (kblk + 15 < wlo || kblk > whi) continue;
            uint32_t ahi[4], alo[4];
            split2(S[2 * kb2][0],     S[2 * kb2][1],     ahi[0], alo[0]);
            split2(S[2 * kb2][2],     S[2 * kb2][3],     ahi[1], alo[1]);
            split2(S[2 * kb2 + 1][0], S[2 * kb2 + 1][1], ahi[2], alo[2]);
            split2(S[2 * kb2 + 1][2], S[2 * kb2 + 1][3], ahi[3], alo[3]);
#pragma unroll
            for (int dbp = 0; dbp < 8; dbp++) {
                uint32_t bvh[4], bvl[4];
                const uint32_t vrow = (uint32_t)(dbp * 16 + (mi >> 1) * 8 + lr) * 144
                                    + (uint32_t)(kb2 * 16 + (mi & 1) * 8) * 2;
                ldsm_x4(bvh, vbh + vrow);
                ldsm_x4(bvl, vbl + vrow);
                mma_bf16(ctx[dbp * 2],     ahi, &bvh[0]);
                mma_bf16(ctx[dbp * 2 + 1], ahi, &bvh[2]);
                mma_bf16(ctx[dbp * 2],     ahi, &bvl[0]);
                mma_bf16(ctx[dbp * 2 + 1], ahi, &bvl[2]);
                mma_bf16(ctx[dbp * 2],     alo, &bvh[0]);
                mma_bf16(ctx[dbp * 2 + 1], alo, &bvh[2]);
            }
        }
    }

    // ---- store ctx (tf32-rounded: feeds out_proj GEMM) ----
    const float inv0 = 1.f / L0;
    const float inv1 = 1.f / L1;
    const int ig0 = i0 + qi0;
    const int ig1 = i0 + qi1;
    if (ig0 < SS) {
        const size_t ro = (size_t)(b * SS + ig0) * DD + h * HDIM;
#pragma unroll
        for (int nb = 0; nb < 16; nb++) {
            const int d = nb * 8 + t4 * 2;
            *(float2*)(ctxp + ro + d) =
                make_float2(tf32r(ctx[nb][0] * inv0), tf32r(ctx[nb][1] * inv0));
        }
    }
    if (ig1 < SS) {
        const size_t ro = (size_t)(b * SS + ig1) * DD + h * HDIM;
#pragma unroll
        for (int nb = 0; nb < 16; nb++) {
            const int d = nb * 8 + t4 * 2;
            *(float2*)(ctxp + ro + d) =
                make_float2(tf32r(ctx[nb][2] * inv1), tf32r(ctx[nb][3] * inv1));
        }
    }
}

// ---------------- residual add + layernorm (LN1; rounded out) --------------
__global__ void __launch_bounds__(256)
add_ln_kernel(const float* __restrict__ x, const float* __restrict__ y,
              const float* __restrict__ w, const float* __restrict__ b,
              float* __restrict__ out)
{
    const int row = blockIdx.x;
    const int t   = threadIdx.x;
    const size_t idx = (size_t)row * DD + t;
    const float v = x[idx] + y[idx];

    __shared__ float s1[8], s2[8];
    float r = v, q = v * v;
#pragma unroll
    for (int o = 16; o; o >>= 1) {
        r += __shfl_xor_sync(0xffffffffu, r, o);
        q += __shfl_xor_sync(0xffffffffu, q, o);
    }
    if ((t & 31) == 0) { s1[t >> 5] = r; s2[t >> 5] = q; }
    __syncthreads();
    float tot  = s1[0]+s1[1]+s1[2]+s1[3]+s1[4]+s1[5]+s1[6]+s1[7];
    float tot2 = s2[0]+s2[1]+s2[2]+s2[3]+s2[4]+s2[5]+s2[6]+s2[7];
    const float mean = tot * (1.f / DD);
    const float var  = tot2 * (1.f / DD) - mean * mean;
    const float inv  = rsqrtf(var + 1e-5f);

    out[idx] = tf32r((v - mean) * inv * w[t] + b[t]);
}

// ---------------- fused LN2 + output head ----------------------------------
__global__ void __launch_bounds__(256)
ln2_head_kernel(const float* __restrict__ x, const float* __restrict__ y,
                const float* __restrict__ w, const float* __restrict__ b,
                const float* __restrict__ wc, float* __restrict__ out)
{
    const int row = blockIdx.x;
    const int t   = threadIdx.x;
    const size_t idx = (size_t)row * DD + t;
    const float v = x[idx] + y[idx];

    __shared__ float s1[8], s2[8], s3[8];
    float r = v, q = v * v;
#pragma unroll
    for (int o = 16; o; o >>= 1) {
        r += __shfl_xor_sync(0xffffffffu, r, o);
        q += __shfl_xor_sync(0xffffffffu, q, o);
    }
    if ((t & 31) == 0) { s1[t >> 5] = r; s2[t >> 5] = q; }
    __syncthreads();
    float tot  = s1[0]+s1[1]+s1[2]+s1[3]+s1[4]+s1[5]+s1[6]+s1[7];
    float tot2 = s2[0]+s2[1]+s2[2]+s2[3]+s2[4]+s2[5]+s2[6]+s2[7];
    const float mean = tot * (1.f / DD);
    const float var  = tot2 * (1.f / DD) - mean * mean;
    const float inv  = rsqrtf(var + 1e-5f);

    const float ln = (v - mean) * inv * w[t] + b[t];
    float d = ln * wc[t];
#pragma unroll
    for (int o = 16; o; o >>= 1) d += __shfl_xor_sync(0xffffffffu, d, o);
    if ((t & 31) == 0) s3[t >> 5] = d;
    __syncthreads();
    if (t == 0) {
        out[row] = s3[0]+s3[1]+s3[2]+s3[3]+s3[4]+s3[5]+s3[6]+s3[7] + wc[256];
    }
}

// ---------------- host launch -----------------------------------------------
template<typename T>
static T* dptr(const void* sym) {
    void* p = nullptr;
    cudaGetSymbolAddress(&p, sym);
    return (T*)p;
}

extern "C" void kernel_launch(void* const* d_in, const int* in_sizes, int n_in,
                              void* d_out, int out_size)
{
    const float* src        = (const float*)d_in[0];
    const float* W_enc      = (const float*)d_in[2];
    const float* b_enc      = (const float*)d_in[3];
    const float* in_proj_w  = (const float*)d_in[4];
    const float* in_proj_b  = (const float*)d_in[5];
    const float* out_proj_w = (const float*)d_in[6];
    const float* out_proj_b = (const float*)d_in[7];
    const float* ln1_w      = (const float*)d_in[8];
    const float* ln1_b      = (const float*)d_in[9];
    const float* lin1_w     = (const float*)d_in[10];
    const float* lin1_b     = (const float*)d_in[11];
    const float* lin2_w     = (const float*)d_in[12];
    const float* lin2_b     = (const float*)d_in[13];
    const float* ln2_w      = (const float*)d_in[14];
    const float* ln2_b      = (const float*)d_in[15];
    const float* fc1_w      = (const float*)d_in[16];
    const float* fc1_b      = (const float*)d_in[17];
    const float* fc2_w      = (const float*)d_in[18];
    const float* fc2_b      = (const float*)d_in[19];
    float* out = (float*)d_out;

    float* x    = dptr<float>(g_x);
    float* ctx  = dptr<float>(g_ctx);
    float* att  = dptr<float>(g_att);
    float* h1   = dptr<float>(g_h1);
    float* ff   = dptr<float>(g_ff);
    float* ff2  = dptr<float>(g_ff2);
    float* wc   = dptr<float>(g_wc);
    float* pos  = dptr<float>(g_pos);
    float* w    = dptr<float>(g_w);
    __nv_bfloat16* qh  = dptr<__nv_bfloat16>(g_qh);
    __nv_bfloat16* ql  = dptr<__nv_bfloat16>(g_ql);
    __nv_bfloat16* kh  = dptr<__nv_bfloat16>(g_kh);
    __nv_bfloat16* kl  = dptr<__nv_bfloat16>(g_kl);
    __nv_bfloat16* vth = dptr<__nv_bfloat16>(g_vth);
    __nv_bfloat16* vtl = dptr<__nv_bfloat16>(g_vtl);

    cudaFuncSetAttribute(tf32_gemm<0>, cudaFuncAttributeMaxDynamicSharedMemorySize, TSM_TOTAL);
    cudaFuncSetAttribute(tf32_gemm<1>, cudaFuncAttributeMaxDynamicSharedMemorySize, TSM_TOTAL);
    cudaFuncSetAttribute(tf32_gemm<2>, cudaFuncAttributeMaxDynamicSharedMemorySize, TSM_TOTAL);
    cudaFuncSetAttribute(tf32_gemm<3>, cudaFuncAttributeMaxDynamicSharedMemorySize, TSM_TOTAL);
    cudaFuncSetAttribute(flash_attn_kernel, cudaFuncAttributeMaxDynamicSharedMemorySize, FSM_TOTAL);

    const dim3 blk(256);

    prep_all_kernel<<<(PN1 + PN3 + 255)/256, blk>>>(
        W_enc, in_proj_w, out_proj_w, lin1_w, lin2_w, w, pos);
    head_prep_kernel<<<16, blk>>>(fc1_w, fc1_b, fc2_w, fc2_b, wc);

    // 1. encoder projection + pos -> x
    tf32_gemm<1><<<dim3(MM/128, DD/128), blk, TSM_TOTAL>>>(
        src, w + WOFF_ENC, b_enc, pos, x, DD,
        nullptr, nullptr, nullptr, nullptr, nullptr, nullptr);
    // 2. qkv projection -> bf16 hi/lo q/k/vT
    tf32_gemm<3><<<dim3(MM/128, (3*DD)/128), blk, TSM_TOTAL>>>(
        x, w + WOFF_QKV, in_proj_b, nullptr, nullptr, 0,
        qh, ql, kh, kl, vth, vtl);
    // 3. flash banded attention -> ctx (128 queries/block, K/V pipelined)
    flash_attn_kernel<<<dim3(16, BB*HH), blk, FSM_TOTAL>>>(
        qh, ql, kh, kl, vth, vtl, ctx);
    // 4. output projection
    tf32_gemm<0><<<dim3(MM/128, DD/128), blk, TSM_TOTAL>>>(
        ctx, w + WOFF_OUT, out_proj_b, nullptr, att, DD,
        nullptr, nullptr, nullptr, nullptr, nullptr, nullptr);
    // 5. add + LN1
    add_ln_kernel<<<MM, blk>>>(x, att, ln1_w, ln1_b, h1);
    // 6. ffn1 + relu
    tf32_gemm<2><<<dim3(MM/128, FFN/128), blk, TSM_TOTAL>>>(
        h1, w + WOFF_L1, lin1_b, nullptr, ff, FFN,
        nullptr, nullptr, nullptr, nullptr, nullptr, nullptr);
    // 7. ffn2
    tf32_gemm<0><<<dim3(MM/128, DD/128), blk, TSM_TOTAL>>>(
        ff, w + WOFF_L2, lin2_b, nullptr, ff2, DD,
        nullptr, nullptr, nullptr, nullptr, nullptr, nullptr);
    // 8. fused add + LN2 + head -> logits [B,S]
    ln2_head_kernel<<<MM, blk>>>(h1, ff2, ln2_w, ln2_b, wc, out);
}

// round 13
// speedup vs baseline: 1.0217x; 1.0217x over previous
#include <cuda_runtime.h>
#include <cuda_bf16.h>
#include <math.h>
#include <stdint.h>

#define BB 8
#define SS 2000
#define MM (BB*SS)          // 16000 rows
#define DD 256
#define HH 2
#define HDIM 128
#define FFN 256
#define WIN 99
#define KK 256              // all GEMMs have K=256
#define QSCALE 0.08838834764831845f

// ---------------- scratch (device globals; no allocation allowed) ----------
__device__ float g_x   [MM*DD];    // encoder out + pos (rounded)
__device__ float g_ctx [MM*DD];    // attention context (rounded)
__device__ float g_att [MM*DD];    // out_proj output (full fp32)
__device__ float g_h1  [MM*DD];    // after LN1 (rounded)
__device__ float g_ff  [MM*FFN];   // relu(ffn1) (rounded)
__device__ float g_ff2 [MM*DD];    // ffn2 (full fp32)
__device__ float g_wc  [260];      // fused head weights + bias
__device__ float g_pos [SS*DD];    // positional encoding table

// bf16 hi/lo q/k/v emitted by qkv GEMM epilogue
// q,k: [bh][s][128]; vT: [bh][d][s]
#define QKN (16*2000*128)
__device__ __nv_bfloat16 g_qh[QKN], g_ql[QKN];
__device__ __nv_bfloat16 g_kh[QKN], g_kl[QKN];
__device__ __nv_bfloat16 g_vth[QKN], g_vtl[QKN];

// tf32-rounded weights, packed: enc | qkv | outproj | lin1 | lin2 (all [N,256])
#define WOFF_ENC 0
#define WOFF_QKV 65536
#define WOFF_OUT 262144
#define WOFF_L1  327680
#define WOFF_L2  393216
#define WTOTAL   458752
__device__ float g_w[WTOTAL];

// ======================= PTX helpers ========================================
__device__ __forceinline__ uint32_t smem_u32(const void* p) {
    uint32_t a;
    asm("{ .reg .u64 t; cvta.to.shared.u64 t, %1; cvt.u32.u64 %0, t; }"
        : "=r"(a) : "l"(p));
    return a;
}

__device__ __forceinline__ float tf32r(float x) {
    uint32_t u;
    asm("cvt.rna.tf32.f32 %0, %1;" : "=r"(u) : "f"(x));
    return __uint_as_float(u);
}

__device__ __forceinline__ uint32_t tf32u(uint32_t x) {
    uint32_t u;
    asm("cvt.rna.tf32.f32 %0, %1;" : "=r"(u) : "f"(__uint_as_float(x)));
    return u;
}

__device__ __forceinline__ void mma_tf32(float* c, const uint32_t* a,
                                         const uint32_t* b) {
    asm volatile(
        "mma.sync.aligned.m16n8k8.row.col.f32.tf32.tf32.f32 "
        "{%0,%1,%2,%3}, {%4,%5,%6,%7}, {%8,%9}, {%0,%1,%2,%3};\n"
        : "+f"(c[0]), "+f"(c[1]), "+f"(c[2]), "+f"(c[3])
        : "r"(a[0]), "r"(a[1]), "r"(a[2]), "r"(a[3]), "r"(b[0]), "r"(b[1]));
}

__device__ __forceinline__ void mma_bf16(float* c, const uint32_t* a,
                                         const uint32_t* b) {
    asm volatile(
        "mma.sync.aligned.m16n8k16.row.col.f32.bf16.bf16.f32 "
        "{%0,%1,%2,%3}, {%4,%5,%6,%7}, {%8,%9}, {%0,%1,%2,%3};\n"
        : "+f"(c[0]), "+f"(c[1]), "+f"(c[2]), "+f"(c[3])
        : "r"(a[0]), "r"(a[1]), "r"(a[2]), "r"(a[3]), "r"(b[0]), "r"(b[1]));
}

__device__ __forceinline__ void ldsm_x4(uint32_t* r, uint32_t addr) {
    asm volatile("ldmatrix.sync.aligned.m8n8.x4.shared.b16 {%0,%1,%2,%3}, [%4];"
        : "=r"(r[0]), "=r"(r[1]), "=r"(r[2]), "=r"(r[3]) : "r"(addr));
}

#define CPASYNC(dst, src) \
    asm volatile("cp.async.cg.shared.global [%0], [%1], 16;" :: "r"(dst), "l"(src))
#define CPCOMMIT() asm volatile("cp.async.commit_group;" ::: "memory")
#define CPWAIT2()  asm volatile("cp.async.wait_group 2;" ::: "memory")
#define CPWAIT1()  asm volatile("cp.async.wait_group 1;" ::: "memory")
#define CPWAIT0()  asm volatile("cp.async.wait_group 0;" ::: "memory")

__device__ __forceinline__ void split2(float a, float b, uint32_t& hi, uint32_t& lo) {
    __nv_bfloat16 ha = __float2bfloat16(a), hb = __float2bfloat16(b);
    __nv_bfloat16 la = __float2bfloat16(a - __bfloat162float(ha));
    __nv_bfloat16 lb = __float2bfloat16(b - __bfloat162float(hb));
    hi = ((uint32_t)(*(uint16_t*)&hb) << 16) | (uint32_t)(*(uint16_t*)&ha);
    lo = ((uint32_t)(*(uint16_t*)&lb) << 16) | (uint32_t)(*(uint16_t*)&la);
}

// ======================= tf32 single-pass GEMM =============================
// C[m,n] = sum_k A[m,k]*B[n,k] + bias[n]; B pre-rounded to tf32.
// Block tile 128x128, 8 warps = 4m x 2n, warp tile 32x64, 3-stage cp.async
// (occupancy already reg-limited to 2 CTAs/SM, so the third stage is free).
// EPI: 0 bias (full fp32 out), 1 bias+pos (round A frags in-kernel; round out),
//      2 bias+relu (round out), 3 qkv bf16 hi/lo emission (q/k [bh][s][d], vT).
#define PITCHB 144          // 36 floats
#define TSA 0
#define TSB 18432
#define TSTAGE 36864
#define TSM_TOTAL (3*TSTAGE)

template<int EPI>
__global__ void __launch_bounds__(256, 2)
tf32_gemm(const float* __restrict__ A, const float* __restrict__ B,
          const float* __restrict__ bias, const float* __restrict__ pos,
          float* __restrict__ outF, int Ntot,
          __nv_bfloat16* __restrict__ qh, __nv_bfloat16* __restrict__ ql,
          __nv_bfloat16* __restrict__ kh, __nv_bfloat16* __restrict__ kl,
          __nv_bfloat16* __restrict__ vth, __nv_bfloat16* __restrict__ vtl)
{
    extern __shared__ char smem[];
    const uint32_t sb = smem_u32(smem);
    const int tid  = threadIdx.x;
    const int wid  = tid >> 5;
    const int lane = tid & 31;
    const int g    = lane >> 2;
    const int t4   = lane & 3;
    const int mi   = lane >> 3;
    const int lr   = lane & 7;
    const int wm   = wid & 3;
    const int wn   = wid >> 2;
    const int row0 = blockIdx.x * 128;
    const int col0 = blockIdx.y * 128;

    float acc[2][8][4];
#pragma unroll
    for (int i = 0; i < 2; i++)
#pragma unroll
        for (int j = 0; j < 8; j++)
#pragma unroll
            for (int k = 0; k < 4; k++) acc[i][j][k] = 0.f;

    auto issue = [&](int st) {
        const int k0 = st * 32;
        const uint32_t base = sb + (st % 3) * TSTAGE;
#pragma unroll
        for (int z = 0; z < 4; z++) {
            const int idx = tid + z * 256;
            const int r = idx >> 3, c = idx & 7;
            CPASYNC(base + TSA + r * PITCHB + c * 16,
                    A + (size_t)(row0 + r) * KK + k0 + c * 4);
        }
#pragma unroll
        for (int z = 0; z < 4; z++) {
            const int idx = tid + z * 256;
            const int r = idx >> 3, c = idx & 7;
            CPASYNC(base + TSB + r * PITCHB + c * 16,
                    B + (size_t)(col0 + r) * KK + k0 + c * 4);
        }
    };

    issue(0); CPCOMMIT();
    issue(1); CPCOMMIT();

#pragma unroll 1
    for (int st = 0; st < 8; st++) {
        if (st < 6)       { issue(st + 2); CPCOMMIT(); CPWAIT2(); }
        else if (st == 6) { CPWAIT1(); }
        else              { CPWAIT0(); }
        __syncthreads();

        const uint32_t base = sb + (st % 3) * TSTAGE;
#pragma unroll
        for (int s = 0; s < 4; s++) {
            uint32_t af[2][4];
#pragma unroll
            for (int mt = 0; mt < 2; mt++) {
                const uint32_t arow = (uint32_t)(wm * 32 + mt * 16 + (mi & 1) * 8 + lr);
                ldsm_x4(af[mt], base + TSA + arow * PITCHB + s * 32 + (mi >> 1) * 16);
                if (EPI == 1) {
#pragma unroll
                    for (int q = 0; q < 4; q++) af[mt][q] = tf32u(af[mt][q]);
                }
            }
            uint32_t bf[4][4];
#pragma unroll
            for (int nt2 = 0; nt2 < 4; nt2++) {
                const uint32_t brow = (uint32_t)(wn * 64 + nt2 * 16 + (mi & 1) * 8 + lr);
                ldsm_x4(bf[nt2], base + TSB + brow * PITCHB + s * 32 + (mi >> 1) * 16);
            }
#pragma unroll
            for (int mt = 0; mt < 2; mt++)
#pragma unroll
                for (int nt = 0; nt < 8; nt++) {
                    uint32_t bb[2] = { bf[nt >> 1][nt & 1], bf[nt >> 1][(nt & 1) + 2] };
                    mma_tf32(acc[mt][nt], af[mt], bb);
                }
        }
        __syncthreads();
    }

    // ---- epilogue ----
#pragma unroll
    for (int mt = 0; mt < 2; mt++) {
#pragma unroll
        for (int nt = 0; nt < 8; nt++) {
            const int c = col0 + wn * 64 + nt * 8 + t4 * 2;
            const float b0 = bias[c], b1 = bias[c + 1];
#pragma unroll
            for (int half = 0; half < 2; half++) {
                const int r = row0 + wm * 32 + mt * 16 + g + half * 8;
                float v0 = acc[mt][nt][half * 2 + 0] + b0;
                float v1 = acc[mt][nt][half * 2 + 1] + b1;
                if (EPI == 2) { v0 = fmaxf(v0, 0.f); v1 = fmaxf(v1, 0.f); }
                if (EPI == 1) {
                    const int s = r % SS;
                    v0 += pos[s * DD + c];
                    v1 += pos[s * DD + c + 1];
                }
                if (EPI == 3) {
                    const int region = c >> 8;         // 0 q, 1 k, 2 v
                    const int hh = (c >> 7) & 1;
                    const int dloc = c & 127;
                    const int bb2 = r / SS;
                    const int s = r - bb2 * SS;
                    const int bh = bb2 * 2 + hh;
                    if (region == 0) { v0 *= QSCALE; v1 *= QSCALE; }
                    if (region <= 1) {
                        uint32_t hp, lp;
                        split2(v0, v1, hp, lp);
                        const size_t o = ((size_t)(bh * 2000 + s)) * 128 + dloc;
                        __nv_bfloat16* H = region ? kh : qh;
                        __nv_bfloat16* L = region ? kl : ql;
                        *(uint32_t*)(H + o) = hp;
                        *(uint32_t*)(L + o) = lp;
                    } else {
                        const __nv_bfloat16 h0 = __float2bfloat16(v0);
                        const __nv_bfloat16 l0 = __float2bfloat16(v0 - __bfloat162float(h0));
                        const __nv_bfloat16 h1 = __float2bfloat16(v1);
                        const __nv_bfloat16 l1 = __float2bfloat16(v1 - __bfloat162float(h1));
                        const size_t o = ((size_t)(bh * 128 + dloc)) * 2000 + s;
                        vth[o] = h0;        vtl[o] = l0;
                        vth[o + 2000] = h1; vtl[o + 2000] = l1;
                    }
                } else {
                    const size_t o = (size_t)r * Ntot + c;
                    if (EPI == 0) *(float2*)(outF + o) = make_float2(v0, v1);
                    else *(float2*)(outF + o) = make_float2(tf32r(v0), tf32r(v1));
                }
            }
        }
    }
}

// ======================= prep kernels ======================================
#define PN1 WTOTAL
#define PN3 (SS*DD)
__global__ void prep_all_kernel(const float* __restrict__ enc,
                                const float* __restrict__ qkvw,
                                const float* __restrict__ outw,
                                const float* __restrict__ l1,
                                const float* __restrict__ l2,
                                float* __restrict__ wdst,
                                float* __restrict__ pdst)
{
    const int i = blockIdx.x * blockDim.x + threadIdx.x;
    if (i < PN1) {
        float v;
        if      (i < WOFF_QKV) v = enc [i];
        else if (i < WOFF_OUT) v = qkvw[i - WOFF_QKV];
        else if (i < WOFF_L1)  v = outw[i - WOFF_OUT];
        else if (i < WOFF_L2)  v = l1  [i - WOFF_L1];
        else                   v = l2  [i - WOFF_L2];
        wdst[i] = tf32r(v);
    } else if (i < PN1 + PN3) {
        const int j = i - PN1;
        const int s = j / DD;
        const int d = j % DD;
        const int p = d >> 1;
        const float div = expf(-(float)(2 * p) * 0.03597789207803197f);
        const float ang = (float)s * div;
        pdst[j] = (d & 1) ? cosf(ang) : sinf(ang);
    }
}

// head prep: wc[d] = sum_j fc2[j]*fc1[j][d]; parallel over j.
__global__ void head_prep_kernel(const float* __restrict__ fc1_w,
                                 const float* __restrict__ fc1_b,
                                 const float* __restrict__ fc2_w,
                                 const float* __restrict__ fc2_b,
                                 float* __restrict__ wc)
{
    __shared__ float sp[16][16];
    const int t  = threadIdx.x;
    const int dl = t & 15;
    const int jg = t >> 4;
    const int d  = blockIdx.x * 16 + dl;
    float s = 0.f;
#pragma unroll
    for (int j = jg * 4; j < jg * 4 + 4; j++)
        s += fc2_w[j] * fc1_w[j * DD + d];
    sp[jg][dl] = s;
    __syncthreads();
    if (t < 16) {
        float tot = 0.f;
#pragma unroll
        for (int j = 0; j < 16; j++) tot += sp[j][t];
        wc[blockIdx.x * 16 + t] = tot;
    }
    if (blockIdx.x == 0 && t == 0) {
        float bb = fc2_b[0];
        for (int j = 0; j < 64; j++) bb += fc2_w[j] * fc1_b[j];
        wc[256] = bb;
    }
}

// ======================= flash-style banded attention (bf16-in) =============
// Round-11 version (validated best). Block: one bh x 64 queries, 4 warps.
// Tiles start ks2 = i0-104. Per-warp valid jj window:
// [max(w*16+5, 104-i0), w*16+119]; fully-masked 16-key blocks skipped.
#define FQH 0
#define FQL 17408
#define FKH 34816
#define FKL 52224
#define FVH 69632
#define FVL 88064
#define FSM_TOTAL 106496

__global__ void __launch_bounds__(128)
flash_attn_kernel(const __nv_bfloat16* __restrict__ qh, const __nv_bfloat16* __restrict__ ql,
                  const __nv_bfloat16* __restrict__ kh, const __nv_bfloat16* __restrict__ kl,
                  const __nv_bfloat16* __restrict__ vth, const __nv_bfloat16* __restrict__ vtl,
                  float* __restrict__ ctxp)
{
    extern __shared__ char sm[];
    const uint32_t sb = smem_u32(sm);
    const int tid  = threadIdx.x;
    const int w    = tid >> 5;
    const int lane = tid & 31;
    const int g    = lane >> 2;
    const int t4   = lane & 3;
    const int mi   = lane >> 3;
    const int lr   = lane & 7;

    const int i0 = blockIdx.x * 64;
    const int bh = blockIdx.y;
    const int b  = bh >> 1;
    const int h  = bh & 1;
    const int ks2 = i0 - 104;
    const size_t qkbase = (size_t)bh * 2000 * 128;
    const size_t vbase  = (size_t)bh * 128 * 2000;

    // ---- issue Q loads ----
#pragma unroll
    for (int z = 0; z < 8; z++) {
        const int idx = z * 128 + tid;
        const int r = idx >> 4, ch = idx & 15;
        const int row = min(i0 + r, SS - 1);
        const size_t go = qkbase + (size_t)row * 128 + ch * 8;
        const uint32_t so = (uint32_t)r * 272 + ch * 16;
        CPASYNC(sb + FQH + so, qh + go);
        CPASYNC(sb + FQL + so, ql + go);
    }
    CPCOMMIT();

    float ctx[16][4];
#pragma unroll
    for (int i = 0; i < 16; i++)
#pragma unroll
        for (int j = 0; j < 4; j++) ctx[i][j] = 0.f;

    const int qi0 = w * 16 + g;
    const int qi1 = qi0 + 8;
    const int vlo0 = max(qi0 + 5, 104 - i0), vhi0 = qi0 + 104;
    const int vlo1 = max(qi1 + 5, 104 - i0), vhi1 = qi1 + 104;
    const int wlo = max(w * 16 + 5, 104 - i0);
    const int whi = w * 16 + 119;
    float m0 = -1e30f, m1 = -1e30f, L0 = 0.f, L1 = 0.f;

#pragma unroll 1
    for (int tt = 0; tt < 3; tt++) {
        __syncthreads();
        // ---- K tile ----
#pragma unroll
        for (int z = 0; z < 8; z++) {
            const int idx = z * 128 + tid;
            const int r = idx >> 4, ch = idx & 15;
            const int j = min(max(ks2 + tt * 64 + r, 0), SS - 1);
            const size_t go = qkbase + (size_t)j * 128 + ch * 8;
            const uint32_t so = (uint32_t)r * 272 + ch * 16;
            CPASYNC(sb + FKH + so, kh + go);
            CPASYNC(sb + FKL + so, kl + go);
        }
        // ---- VT tile ----
#pragma unroll
        for (int z = 0; z < 8; z++) {
            const int idx = z * 128 + tid;
            const int r = idx >> 3, ch = idx & 7;
            const int sc = max(0, min(ks2 + tt * 64 + ch * 8, SS - 8));
            const size_t go = vbase + (size_t)r * 2000 + sc;
            const uint32_t so = (uint32_t)r * 144 + ch * 16;
            CPASYNC(sb + FVH + so, vth + go);
            CPASYNC(sb + FVL + so, vtl + go);
        }
        CPCOMMIT();
        CPWAIT0();
        __syncthreads();

        // ---- QK (skip fully-masked 16-key blocks per warp) ----
        float S[8][4];
#pragma unroll
        for (int i = 0; i < 8; i++)
#pragma unroll
            for (int j = 0; j < 4; j++) S[i][j] = 0.f;

#pragma unroll
        for (int kb = 0; kb < 8; kb++) {
            uint32_t aqh[4], aql[4];
            const uint32_t arow = (uint32_t)(w * 16 + (mi & 1) * 8 + lr) * 272
                                + (uint32_t)(kb * 16 + (mi >> 1) * 8) * 2;
            ldsm_x4(aqh, sb + FQH + arow);
            ldsm_x4(aql, sb + FQL + arow);
#pragma unroll
            for (int nbp = 0; nbp < 4; nbp++) {
                const int kblk = tt * 64 + nbp * 16;
                if (kblk + 15 < wlo || kblk > whi) continue;
                uint32_t bkh[4], bkl[4];
                const uint32_t brow = (uint32_t)(nbp * 16 + (mi >> 1) * 8 + lr) * 272
                                    + (uint32_t)(kb * 16 + (mi & 1) * 8) * 2;
                ldsm_x4(bkh, sb + FKH + brow);
                ldsm_x4(bkl, sb + FKL + brow);
                mma_bf16(S[nbp * 2],     aqh, &bkh[0]);
                mma_bf16(S[nbp * 2 + 1], aqh, &bkh[2]);
                mma_bf16(S[nbp * 2],     aqh, &bkl[0]);
                mma_bf16(S[nbp * 2 + 1], aqh, &bkl[2]);
                mma_bf16(S[nbp * 2],     aql, &bkh[0]);
                mma_bf16(S[nbp * 2 + 1], aql, &bkh[2]);
            }
        }

        // ---- band mask + running softmax ----
        float mx0 = -1e30f, mx1 = -1e30f;
#pragma unroll
        for (int nb = 0; nb < 8; nb++) {
            const int jj = tt * 64 + nb * 8 + t4 * 2;
            if (jj < vlo0     || jj > vhi0)     S[nb][0] = -1e30f;
            if (jj + 1 < vlo0 || jj + 1 > vhi0) S[nb][1] = -1e30f;
            if (jj < vlo1     || jj > vhi1)     S[nb][2] = -1e30f;
            if (jj + 1 < vlo1 || jj + 1 > vhi1) S[nb][3] = -1e30f;
            mx0 = fmaxf(mx0, fmaxf(S[nb][0], S[nb][1]));
            mx1 = fmaxf(mx1, fmaxf(S[nb][2], S[nb][3]));
        }
        mx0 = fmaxf(mx0, __shfl_xor_sync(0xffffffffu, mx0, 1));
        mx0 = fmaxf(mx0, __shfl_xor_sync(0xffffffffu, mx0, 2));
        mx1 = fmaxf(mx1, __shfl_xor_sync(0xffffffffu, mx1, 1));
        mx1 = fmaxf(mx1, __shfl_xor_sync(0xffffffffu, mx1, 2));

        const float mn0 = fmaxf(m0, mx0);
        const float mn1 = fmaxf(m1, mx1);
        const float f0 = __expf(m0 - mn0);
        const float f1 = __expf(m1 - mn1);

        float sum0 = 0.f, sum1 = 0.f;
#pragma unroll
        for (int nb = 0; nb < 8; nb++) {
            float e0 = (S[nb][0] == -1e30f) ? 0.f : __expf(S[nb][0] - mn0);
            float e1 = (S[nb][1] == -1e30f) ? 0.f : __expf(S[nb][1] - mn0);
            float e2 = (S[nb][2] == -1e30f) ? 0.f : __expf(S[nb][2] - mn1);
            float e3 = (S[nb][3] == -1e30f) ? 0.f : __expf(S[nb][3] - mn1);
            S[nb][0] = e0; S[nb][1] = e1; S[nb][2] = e2; S[nb][3] = e3;
            sum0 += e0 + e1;
            sum1 += e2 + e3;
        }
        sum0 += __shfl_xor_sync(0xffffffffu, sum0, 1);
        sum0 += __shfl_xor_sync(0xffffffffu, sum0, 2);
        sum1 += __shfl_xor_sync(0xffffffffu, sum1, 1);
        sum1 += __shfl_xor_sync(0xffffffffu, sum1, 2);
        L0 = L0 * f0 + sum0;
        L1 = L1 * f1 + sum1;
        m0 = mn0; m1 = mn1;

#pragma unroll
        for (int nb = 0; nb < 16; nb++) {
            ctx[nb][0] *= f0; ctx[nb][1] *= f0;
            ctx[nb][2] *= f1; ctx[nb][3] *= f1;
        }

        // ---- PV (skip fully-masked 16-key blocks per warp) ----
#pragma unroll
        for (int kb2 = 0; kb2 < 4; kb2++) {
            const int kblk = tt * 64 + kb2 * 16;
            if (kblk + 15 < wlo || kblk > whi) continue;
            uint32_t ahi[4], alo[4];
            split2(S[2 * kb2][0],     S[2 * kb2][1],     ahi[0], alo[0]);
            split2(S[2 * kb2][2],     S[2 * kb2][3],     ahi[1], alo[1]);
            split2(S[2 * kb2 + 1][0], S[2 * kb2 + 1][1], ahi[2], alo[2]);
            split2(S[2 * kb2 + 1][2], S[2 * kb2 + 1][3], ahi[3], alo[3]);
#pragma unroll
            for (int dbp = 0; dbp < 8; dbp++) {
                uint32_t bvh[4], bvl[4];
                const uint32_t vrow = (uint32_t)(dbp * 16 + (mi >> 1) * 8 + lr) * 144
                                    + (uint32_t)(kb2 * 16 + (mi & 1) * 8) * 2;
                ldsm_x4(bvh, sb + FVH + vrow);
                ldsm_x4(bvl, sb + FVL + vrow);
                mma_bf16(ctx[dbp * 2],     ahi, &bvh[0]);
                mma_bf16(ctx[dbp * 2 + 1], ahi, &bvh[2]);
                mma_bf16(ctx[dbp * 2],     ahi, &bvl[0]);
                mma_bf16(ctx[dbp * 2 + 1], ahi, &bvl[2]);
                mma_bf16(ctx[dbp * 2],     alo, &bvh[0]);
                mma_bf16(ctx[dbp * 2 + 1], alo, &bvh[2]);
            }
        }
    }

    // ---- store ctx (tf32-rounded: feeds out_proj GEMM) ----
    const float inv0 = 1.f / L0;
    const float inv1 = 1.f / L1;
    const int ig0 = i0 + qi0;
    const int ig1 = i0 + qi1;
    if (ig0 < SS) {
        const size_t ro = (size_t)(b * SS + ig0) * DD + h * HDIM;
#pragma unroll
        for (int nb = 0; nb < 16; nb++) {
            const int d = nb * 8 + t4 * 2;
            *(float2*)(ctxp + ro + d) =
                make_float2(tf32r(ctx[nb][0] * inv0), tf32r(ctx[nb][1] * inv0));
        }
    }
    if (ig1 < SS) {
        const size_t ro = (size_t)(b * SS + ig1) * DD + h * HDIM;
#pragma unroll
        for (int nb = 0; nb < 16; nb++) {
            const int d = nb * 8 + t4 * 2;
            *(float2*)(ctxp + ro + d) =
                make_float2(tf32r(ctx[nb][2] * inv1), tf32r(ctx[nb][3] * inv1));
        }
    }
}

// ---------------- residual add + layernorm (LN1; rounded out) --------------
__global__ void __launch_bounds__(256)
add_ln_kernel(const float* __restrict__ x, const float* __restrict__ y,
              const float* __restrict__ w, const float* __restrict__ b,
              float* __restrict__ out)
{
    const int row = blockIdx.x;
    const int t   = threadIdx.x;
    const size_t idx = (size_t)row * DD + t;
    const float v = x[idx] + y[idx];

    __shared__ float s1[8], s2[8];
    float r = v, q = v * v;
#pragma unroll
    for (int o = 16; o; o >>= 1) {
        r += __shfl_xor_sync(0xffffffffu, r, o);
        q += __shfl_xor_sync(0xffffffffu, q, o);
    }
    if ((t & 31) == 0) { s1[t >> 5] = r; s2[t >> 5] = q; }
    __syncthreads();
    float tot  = s1[0]+s1[1]+s1[2]+s1[3]+s1[4]+s1[5]+s1[6]+s1[7];
    float tot2 = s2[0]+s2[1]+s2[2]+s2[3]+s2[4]+s2[5]+s2[6]+s2[7];
    const float mean = tot * (1.f / DD);
    const float var  = tot2 * (1.f / DD) - mean * mean;
    const float inv  = rsqrtf(var + 1e-5f);

    out[idx] = tf32r((v - mean) * inv * w[t] + b[t]);
}

// ---------------- fused LN2 + output head ----------------------------------
__global__ void __launch_bounds__(256)
ln2_head_kernel(const float* __restrict__ x, const float* __restrict__ y,
                const float* __restrict__ w, const float* __restrict__ b,
                const float* __restrict__ wc, float* __restrict__ out)
{
    const int row = blockIdx.x;
    const int t   = threadIdx.x;
    const size_t idx = (size_t)row * DD + t;
    const float v = x[idx] + y[idx];

    __shared__ float s1[8], s2[8], s3[8];
    float r = v, q = v * v;
#pragma unroll
    for (int o = 16; o; o >>= 1) {
        r += __shfl_xor_sync(0xffffffffu, r, o);
        q += __shfl_xor_sync(0xffffffffu, q, o);
    }
    if ((t & 31) == 0) { s1[t >> 5] = r; s2[t >> 5] = q; }
    __syncthreads();
    float tot  = s1[0]+s1[1]+s1[2]+s1[3]+s1[4]+s1[5]+s1[6]+s1[7];
    float tot2 = s2[0]+s2[1]+s2[2]+s2[3]+s2[4]+s2[5]+s2[6]+s2[7];
    const float mean = tot * (1.f / DD);
    const float var  = tot2 * (1.f / DD) - mean * mean;
    const float inv  = rsqrtf(var + 1e-5f);

    const float ln = (v - mean) * inv * w[t] + b[t];
    float d = ln * wc[t];
#pragma unroll
    for (int o = 16; o; o >>= 1) d += __shfl_xor_sync(0xffffffffu, d, o);
    if ((t & 31) == 0) s3[t >> 5] = d;
    __syncthreads();
    if (t == 0) {
        out[row] = s3[0]+s3[1]+s3[2]+s3[3]+s3[4]+s3[5]+s3[6]+s3[7] + wc[256];
    }
}

// ---------------- host launch -----------------------------------------------
template<typename T>
static T* dptr(const void* sym) {
    void* p = nullptr;
    cudaGetSymbolAddress(&p, sym);
    return (T*)p;
}

extern "C" void kernel_launch(void* const* d_in, const int* in_sizes, int n_in,
                              void* d_out, int out_size)
{
    const float* src        = (const float*)d_in[0];
    const float* W_enc      = (const float*)d_in[2];
    const float* b_enc      = (const float*)d_in[3];
    const float* in_proj_w  = (const float*)d_in[4];
    const float* in_proj_b  = (const float*)d_in[5];
    const float* out_proj_w = (const float*)d_in[6];
    const float* out_proj_b = (const float*)d_in[7];
    const float* ln1_w      = (const float*)d_in[8];
    const float* ln1_b      = (const float*)d_in[9];
    const float* lin1_w     = (const float*)d_in[10];
    const float* lin1_b     = (const float*)d_in[11];
    const float* lin2_w     = (const float*)d_in[12];
    const float* lin2_b     = (const float*)d_in[13];
    const float* ln2_w      = (const float*)d_in[14];
    const float* ln2_b      = (const float*)d_in[15];
    const float* fc1_w      = (const float*)d_in[16];
    const float* fc1_b      = (const float*)d_in[17];
    const float* fc2_w      = (const float*)d_in[18];
    const float* fc2_b      = (const float*)d_in[19];
    float* out = (float*)d_out;

    float* x    = dptr<float>(g_x);
    float* ctx  = dptr<float>(g_ctx);
    float* att  = dptr<float>(g_att);
    float* h1   = dptr<float>(g_h1);
    float* ff   = dptr<float>(g_ff);
    float* ff2  = dptr<float>(g_ff2);
    float* wc   = dptr<float>(g_wc);
    float* pos  = dptr<float>(g_pos);
    float* w    = dptr<float>(g_w);
    __nv_bfloat16* qh  = dptr<__nv_bfloat16>(g_qh);
    __nv_bfloat16* ql  = dptr<__nv_bfloat16>(g_ql);
    __nv_bfloat16* kh  = dptr<__nv_bfloat16>(g_kh);
    __nv_bfloat16* kl  = dptr<__nv_bfloat16>(g_kl);
    __nv_bfloat16* vth = dptr<__nv_bfloat16>(g_vth);
    __nv_bfloat16* vtl = dptr<__nv_bfloat16>(g_vtl);

    cudaFuncSetAttribute(tf32_gemm<0>, cudaFuncAttributeMaxDynamicSharedMemorySize, TSM_TOTAL);
    cudaFuncSetAttribute(tf32_gemm<1>, cudaFuncAttributeMaxDynamicSharedMemorySize, TSM_TOTAL);
    cudaFuncSetAttribute(tf32_gemm<2>, cudaFuncAttributeMaxDynamicSharedMemorySize, TSM_TOTAL);
    cudaFuncSetAttribute(tf32_gemm<3>, cudaFuncAttributeMaxDynamicSharedMemorySize, TSM_TOTAL);
    cudaFuncSetAttribute(flash_attn_kernel, cudaFuncAttributeMaxDynamicSharedMemorySize, FSM_TOTAL);

    const dim3 blk(256);

    prep_all_kernel<<<(PN1 + PN3 + 255)/256, blk>>>(
        W_enc, in_proj_w, out_proj_w, lin1_w, lin2_w, w, pos);
    head_prep_kernel<<<16, blk>>>(fc1_w, fc1_b, fc2_w, fc2_b, wc);

    // 1. encoder projection + pos -> x
    tf32_gemm<1><<<dim3(MM/128, DD/128), blk, TSM_TOTAL>>>(
        src, w + WOFF_ENC, b_enc, pos, x, DD,
        nullptr, nullptr, nullptr, nullptr, nullptr, nullptr);
    // 2. qkv projection -> bf16 hi/lo q/k/vT
    tf32_gemm<3><<<dim3(MM/128, (3*DD)/128), blk, TSM_TOTAL>>>(
        x, w + WOFF_QKV, in_proj_b, nullptr, nullptr, 0,
        qh, ql, kh, kl, vth, vtl);
    // 3. flash banded attention -> ctx
    flash_attn_kernel<<<dim3(32, BB*HH), 128, FSM_TOTAL>>>(
        qh, ql, kh, kl, vth, vtl, ctx);
    // 4. output projection
    tf32_gemm<0><<<dim3(MM/128, DD/128), blk, TSM_TOTAL>>>(
        ctx, w + WOFF_OUT, out_proj_b, nullptr, att, DD,
        nullptr, nullptr, nullptr, nullptr, nullptr, nullptr);
    // 5. add + LN1
    add_ln_kernel<<<MM, blk>>>(x, att, ln1_w, ln1_b, h1);
    // 6. ffn1 + relu
    tf32_gemm<2><<<dim3(MM/128, FFN/128), blk, TSM_TOTAL>>>(
        h1, w + WOFF_L1, lin1_b, nullptr, ff, FFN,
        nullptr, nullptr, nullptr, nullptr, nullptr, nullptr);
    // 7. ffn2
    tf32_gemm<0><<<dim3(MM/128, DD/128), blk, TSM_TOTAL>>>(
        ff, w + WOFF_L2, lin2_b, nullptr, ff2, DD,
        nullptr, nullptr, nullptr, nullptr, nullptr, nullptr);
    // 8. fused add + LN2 + head -> logits [B,S]
    ln2_head_kernel<<<MM, blk>>>(h1, ff2, ln2_w, ln2_b, wc, out);
}

// round 14
// speedup vs baseline: 1.1427x; 1.1185x over previous
#include <cuda_runtime.h>
#include <cuda_bf16.h>
#include <math.h>
#include <stdint.h>

#define BB 8
#define SS 2000
#define MM (BB*SS)          // 16000 rows
#define DD 256
#define HH 2
#define HDIM 128
#define FFN 256
#define WIN 99
#define KK 256              // all GEMMs have K=256
#define QSCALE 0.08838834764831845f

// ---------------- scratch (device globals; no allocation allowed) ----------
__device__ float g_x   [MM*DD];    // encoder out + pos (rounded)
__device__ float g_ctx [MM*DD];    // attention context (rounded)
__device__ float g_att [MM*DD];    // out_proj output (full fp32)
__device__ float g_h1  [MM*DD];    // after LN1 (rounded)
__device__ float g_ff  [MM*FFN];   // relu(ffn1) (rounded)
__device__ float g_ff2 [MM*DD];    // ffn2 (full fp32)
__device__ float g_wc  [260];      // fused head weights + bias
__device__ float g_pos [SS*DD];    // positional encoding table

// bf16 hi/lo q/k/v emitted by qkv GEMM epilogue
// q,k: [bh][s][128]; vT: [bh][d][s]
#define QKN (16*2000*128)
__device__ __nv_bfloat16 g_qh[QKN], g_ql[QKN];
__device__ __nv_bfloat16 g_kh[QKN], g_kl[QKN];
__device__ __nv_bfloat16 g_vth[QKN], g_vtl[QKN];

// tf32-rounded weights, packed: enc | qkv | outproj | lin1 | lin2 (all [N,256])
#define WOFF_ENC 0
#define WOFF_QKV 65536
#define WOFF_OUT 262144
#define WOFF_L1  327680
#define WOFF_L2  393216
#define WTOTAL   458752
__device__ float g_w[WTOTAL];

// ======================= PTX helpers ========================================
__device__ __forceinline__ uint32_t smem_u32(const void* p) {
    uint32_t a;
    asm("{ .reg .u64 t; cvta.to.shared.u64 t, %1; cvt.u32.u64 %0, t; }"
        : "=r"(a) : "l"(p));
    return a;
}

__device__ __forceinline__ float tf32r(float x) {
    uint32_t u;
    asm("cvt.rna.tf32.f32 %0, %1;" : "=r"(u) : "f"(x));
    return __uint_as_float(u);
}

__device__ __forceinline__ uint32_t tf32u(uint32_t x) {
    uint32_t u;
    asm("cvt.rna.tf32.f32 %0, %1;" : "=r"(u) : "f"(__uint_as_float(x)));
    return u;
}

__device__ __forceinline__ void mma_tf32(float* c, const uint32_t* a,
                                         const uint32_t* b) {
    asm volatile(
        "mma.sync.aligned.m16n8k8.row.col.f32.tf32.tf32.f32 "
        "{%0,%1,%2,%3}, {%4,%5,%6,%7}, {%8,%9}, {%0,%1,%2,%3};\n"
        : "+f"(c[0]), "+f"(c[1]), "+f"(c[2]), "+f"(c[3])
        : "r"(a[0]), "r"(a[1]), "r"(a[2]), "r"(a[3]), "r"(b[0]), "r"(b[1]));
}

__device__ __forceinline__ void mma_bf16(float* c, const uint32_t* a,
                                         const uint32_t* b) {
    asm volatile(
        "mma.sync.aligned.m16n8k16.row.col.f32.bf16.bf16.f32 "
        "{%0,%1,%2,%3}, {%4,%5,%6,%7}, {%8,%9}, {%0,%1,%2,%3};\n"
        : "+f"(c[0]), "+f"(c[1]), "+f"(c[2]), "+f"(c[3])
        : "r"(a[0]), "r"(a[1]), "r"(a[2]), "r"(a[3]), "r"(b[0]), "r"(b[1]));
}

__device__ __forceinline__ void ldsm_x4(uint32_t* r, uint32_t addr) {
    asm volatile("ldmatrix.sync.aligned.m8n8.x4.shared.b16 {%0,%1,%2,%3}, [%4];"
        : "=r"(r[0]), "=r"(r[1]), "=r"(r[2]), "=r"(r[3]) : "r"(addr));
}

#define CPASYNC(dst, src) \
    asm volatile("cp.async.cg.shared.global [%0], [%1], 16;" :: "r"(dst), "l"(src))
#define CPCOMMIT() asm volatile("cp.async.commit_group;" ::: "memory")
#define CPWAIT1()  asm volatile("cp.async.wait_group 1;" ::: "memory")
#define CPWAIT0()  asm volatile("cp.async.wait_group 0;" ::: "memory")

__device__ __forceinline__ void split2(float a, float b, uint32_t& hi, uint32_t& lo) {
    __nv_bfloat16 ha = __float2bfloat16(a), hb = __float2bfloat16(b);
    __nv_bfloat16 la = __float2bfloat16(a - __bfloat162float(ha));
    __nv_bfloat16 lb = __float2bfloat16(b - __bfloat162float(hb));
    hi = ((uint32_t)(*(uint16_t*)&hb) << 16) | (uint32_t)(*(uint16_t*)&ha);
    lo = ((uint32_t)(*(uint16_t*)&lb) << 16) | (uint32_t)(*(uint16_t*)&la);
}

// ======================= tf32 single-pass GEMM (round-11, 2-stage) ==========
// C[m,n] = sum_k A[m,k]*B[n,k] + bias[n]; B pre-rounded to tf32.
// Block tile 128x128, 8 warps = 4m x 2n, warp tile 32x64, 2-stage cp.async.
// EPI: 0 bias (full fp32 out), 1 bias+pos (round A frags in-kernel; round out),
//      2 bias+relu (round out), 3 qkv bf16 hi/lo emission (q/k [bh][s][d], vT).
#define PITCHB 144          // 36 floats
#define TSA 0
#define TSB 18432
#define TSTAGE 36864
#define TSM_TOTAL (2*TSTAGE)

template<int EPI>
__global__ void __launch_bounds__(256, 2)
tf32_gemm(const float* __restrict__ A, const float* __restrict__ B,
          const float* __restrict__ bias, const float* __restrict__ pos,
          float* __restrict__ outF, int Ntot,
          __nv_bfloat16* __restrict__ qh, __nv_bfloat16* __restrict__ ql,
          __nv_bfloat16* __restrict__ kh, __nv_bfloat16* __restrict__ kl,
          __nv_bfloat16* __restrict__ vth, __nv_bfloat16* __restrict__ vtl)
{
    extern __shared__ char smem[];
    const uint32_t sb = smem_u32(smem);
    const int tid  = threadIdx.x;
    const int wid  = tid >> 5;
    const int lane = tid & 31;
    const int g    = lane >> 2;
    const int t4   = lane & 3;
    const int mi   = lane >> 3;
    const int lr   = lane & 7;
    const int wm   = wid & 3;
    const int wn   = wid >> 2;
    const int row0 = blockIdx.x * 128;
    const int col0 = blockIdx.y * 128;

    float acc[2][8][4];
#pragma unroll
    for (int i = 0; i < 2; i++)
#pragma unroll
        for (int j = 0; j < 8; j++)
#pragma unroll
            for (int k = 0; k < 4; k++) acc[i][j][k] = 0.f;

    auto issue = [&](int st) {
        const int k0 = st * 32;
        const uint32_t base = sb + (st & 1) * TSTAGE;
#pragma unroll
        for (int z = 0; z < 4; z++) {
            const int idx = tid + z * 256;
            const int r = idx >> 3, c = idx & 7;
            CPASYNC(base + TSA + r * PITCHB + c * 16,
                    A + (size_t)(row0 + r) * KK + k0 + c * 4);
        }
#pragma unroll
        for (int z = 0; z < 4; z++) {
            const int idx = tid + z * 256;
            const int r = idx >> 3, c = idx & 7;
            CPASYNC(base + TSB + r * PITCHB + c * 16,
                    B + (size_t)(col0 + r) * KK + k0 + c * 4);
        }
    };

    issue(0); CPCOMMIT();

#pragma unroll 1
    for (int st = 0; st < 8; st++) {
        if (st < 7) { issue(st + 1); CPCOMMIT(); CPWAIT1(); }
        else        { CPWAIT0(); }
        __syncthreads();

        const uint32_t base = sb + (st & 1) * TSTAGE;
#pragma unroll
        for (int s = 0; s < 4; s++) {
            uint32_t af[2][4];
#pragma unroll
            for (int mt = 0; mt < 2; mt++) {
                const uint32_t arow = (uint32_t)(wm * 32 + mt * 16 + (mi & 1) * 8 + lr);
                ldsm_x4(af[mt], base + TSA + arow * PITCHB + s * 32 + (mi >> 1) * 16);
                if (EPI == 1) {
#pragma unroll
                    for (int q = 0; q < 4; q++) af[mt][q] = tf32u(af[mt][q]);
                }
            }
            uint32_t bf[4][4];
#pragma unroll
            for (int nt2 = 0; nt2 < 4; nt2++) {
                const uint32_t brow = (uint32_t)(wn * 64 + nt2 * 16 + (mi & 1) * 8 + lr);
                ldsm_x4(bf[nt2], base + TSB + brow * PITCHB + s * 32 + (mi >> 1) * 16);
            }
#pragma unroll
            for (int mt = 0; mt < 2; mt++)
#pragma unroll
                for (int nt = 0; nt < 8; nt++) {
                    uint32_t bb[2] = { bf[nt >> 1][nt & 1], bf[nt >> 1][(nt & 1) + 2] };
                    mma_tf32(acc[mt][nt], af[mt], bb);
                }
        }
        __syncthreads();
    }

    // ---- epilogue ----
#pragma unroll
    for (int mt = 0; mt < 2; mt++) {
#pragma unroll
        for (int nt = 0; nt < 8; nt++) {
            const int c = col0 + wn * 64 + nt * 8 + t4 * 2;
            const float b0 = bias[c], b1 = bias[c + 1];
#pragma unroll
            for (int half = 0; half < 2; half++) {
                const int r = row0 + wm * 32 + mt * 16 + g + half * 8;
                float v0 = acc[mt][nt][half * 2 + 0] + b0;
                float v1 = acc[mt][nt][half * 2 + 1] + b1;
                if (EPI == 2) { v0 = fmaxf(v0, 0.f); v1 = fmaxf(v1, 0.f); }
                if (EPI == 1) {
                    const int s = r % SS;
                    v0 += pos[s * DD + c];
                    v1 += pos[s * DD + c + 1];
                }
                if (EPI == 3) {
                    const int region = c >> 8;         // 0 q, 1 k, 2 v
                    const int hh = (c >> 7) & 1;
                    const int dloc = c & 127;
                    const int bb2 = r / SS;
                    const int s = r - bb2 * SS;
                    const int bh = bb2 * 2 + hh;
                    if (region == 0) { v0 *= QSCALE; v1 *= QSCALE; }
                    if (region <= 1) {
                        uint32_t hp, lp;
                        split2(v0, v1, hp, lp);
                        const size_t o = ((size_t)(bh * 2000 + s)) * 128 + dloc;
                        __nv_bfloat16* H = region ? kh : qh;
                        __nv_bfloat16* L = region ? kl : ql;
                        *(uint32_t*)(H + o) = hp;
                        *(uint32_t*)(L + o) = lp;
                    } else {
                        const __nv_bfloat16 h0 = __float2bfloat16(v0);
                        const __nv_bfloat16 l0 = __float2bfloat16(v0 - __bfloat162float(h0));
                        const __nv_bfloat16 h1 = __float2bfloat16(v1);
                        const __nv_bfloat16 l1 = __float2bfloat16(v1 - __bfloat162float(h1));
                        const size_t o = ((size_t)(bh * 128 + dloc)) * 2000 + s;
                        vth[o] = h0;        vtl[o] = l0;
                        vth[o + 2000] = h1; vtl[o + 2000] = l1;
                    }
                } else {
                    const size_t o = (size_t)r * Ntot + c;
                    if (EPI == 0) *(float2*)(outF + o) = make_float2(v0, v1);
                    else *(float2*)(outF + o) = make_float2(tf32r(v0), tf32r(v1));
                }
            }
        }
    }
}

// ======================= prep kernels ======================================
#define PN1 WTOTAL
#define PN3 (SS*DD)
__global__ void prep_all_kernel(const float* __restrict__ enc,
                                const float* __restrict__ qkvw,
                                const float* __restrict__ outw,
                                const float* __restrict__ l1,
                                const float* __restrict__ l2,
                                float* __restrict__ wdst,
                                float* __restrict__ pdst)
{
    const int i = blockIdx.x * blockDim.x + threadIdx.x;
    if (i < PN1) {
        float v;
        if      (i < WOFF_QKV) v = enc [i];
        else if (i < WOFF_OUT) v = qkvw[i - WOFF_QKV];
        else if (i < WOFF_L1)  v = outw[i - WOFF_OUT];
        else if (i < WOFF_L2)  v = l1  [i - WOFF_L1];
        else                   v = l2  [i - WOFF_L2];
        wdst[i] = tf32r(v);
    } else if (i < PN1 + PN3) {
        const int j = i - PN1;
        const int s = j / DD;
        const int d = j % DD;
        const int p = d >> 1;
        const float div = expf(-(float)(2 * p) * 0.03597789207803197f);
        const float ang = (float)s * div;
        pdst[j] = (d & 1) ? cosf(ang) : sinf(ang);
    }
}

// head prep: wc[d] = sum_j fc2[j]*fc1[j][d]; parallel over j.
__global__ void head_prep_kernel(const float* __restrict__ fc1_w,
                                 const float* __restrict__ fc1_b,
                                 const float* __restrict__ fc2_w,
                                 const float* __restrict__ fc2_b,
                                 float* __restrict__ wc)
{
    __shared__ float sp[16][16];
    const int t  = threadIdx.x;
    const int dl = t & 15;
    const int jg = t >> 4;
    const int d  = blockIdx.x * 16 + dl;
    float s = 0.f;
#pragma unroll
    for (int j = jg * 4; j < jg * 4 + 4; j++)
        s += fc2_w[j] * fc1_w[j * DD + d];
    sp[jg][dl] = s;
    __syncthreads();
    if (t < 16) {
        float tot = 0.f;
#pragma unroll
        for (int j = 0; j < 16; j++) tot += sp[j][t];
        wc[blockIdx.x * 16 + t] = tot;
    }
    if (blockIdx.x == 0 && t == 0) {
        float bb = fc2_b[0];
        for (int j = 0; j < 64; j++) bb += fc2_w[j] * fc1_b[j];
        wc[256] = bb;
    }
}

// ======================= flash-style banded attention (round-11) ============
#define FQH 0
#define FQL 17408
#define FKH 34816
#define FKL 52224
#define FVH 69632
#define FVL 88064
#define FSM_TOTAL 106496

__global__ void __launch_bounds__(128)
flash_attn_kernel(const __nv_bfloat16* __restrict__ qh, const __nv_bfloat16* __restrict__ ql,
                  const __nv_bfloat16* __restrict__ kh, const __nv_bfloat16* __restrict__ kl,
                  const __nv_bfloat16* __restrict__ vth, const __nv_bfloat16* __restrict__ vtl,
                  float* __restrict__ ctxp)
{
    extern __shared__ char sm[];
    const uint32_t sb = smem_u32(sm);
    const int tid  = threadIdx.x;
    const int w    = tid >> 5;
    const int lane = tid & 31;
    const int g    = lane >> 2;
    const int t4   = lane & 3;
    const int mi   = lane >> 3;
    const int lr   = lane & 7;

    const int i0 = blockIdx.x * 64;
    const int bh = blockIdx.y;
    const int b  = bh >> 1;
    const int h  = bh & 1;
    const int ks2 = i0 - 104;
    const size_t qkbase = (size_t)bh * 2000 * 128;
    const size_t vbase  = (size_t)bh * 128 * 2000;

    // ---- issue Q loads ----
#pragma unroll
    for (int z = 0; z < 8; z++) {
        const int idx = z * 128 + tid;
        const int r = idx >> 4, ch = idx & 15;
        const int row = min(i0 + r, SS - 1);
        const size_t go = qkbase + (size_t)row * 128 + ch * 8;
        const uint32_t so = (uint32_t)r * 272 + ch * 16;
        CPASYNC(sb + FQH + so, qh + go);
        CPASYNC(sb + FQL + so, ql + go);
    }
    CPCOMMIT();

    float ctx[16][4];
#pragma unroll
    for (int i = 0; i < 16; i++)
#pragma unroll
        for (int j = 0; j < 4; j++) ctx[i][j] = 0.f;

    const int qi0 = w * 16 + g;
    const int qi1 = qi0 + 8;
    const int vlo0 = max(qi0 + 5, 104 - i0), vhi0 = qi0 + 104;
    const int vlo1 = max(qi1 + 5, 104 - i0), vhi1 = qi1 + 104;
    const int wlo = max(w * 16 + 5, 104 - i0);
    const int whi = w * 16 + 119;
    float m0 = -1e30f, m1 = -1e30f, L0 = 0.f, L1 = 0.f;

#pragma unroll 1
    for (int tt = 0; tt < 3; tt++) {
        __syncthreads();
        // ---- K tile ----
#pragma unroll
        for (int z = 0; z < 8; z++) {
            const int idx = z * 128 + tid;
            const int r = idx >> 4, ch = idx & 15;
            const int j = min(max(ks2 + tt * 64 + r, 0), SS - 1);
            const size_t go = qkbase + (size_t)j * 128 + ch * 8;
            const uint32_t so = (uint32_t)r * 272 + ch * 16;
            CPASYNC(sb + FKH + so, kh + go);
            CPASYNC(sb + FKL + so, kl + go);
        }
        // ---- VT tile ----
#pragma unroll
        for (int z = 0; z < 8; z++) {
            const int idx = z * 128 + tid;
            const int r = idx >> 3, ch = idx & 7;
            const int sc = max(0, min(ks2 + tt * 64 + ch * 8, SS - 8));
            const size_t go = vbase + (size_t)r * 2000 + sc;
            const uint32_t so = (uint32_t)r * 144 + ch * 16;
            CPASYNC(sb + FVH + so, vth + go);
            CPASYNC(sb + FVL + so, vtl + go);
        }
        CPCOMMIT();
        CPWAIT0();
        __syncthreads();

        // ---- QK (skip fully-masked 16-key blocks per warp) ----
        float S[8][4];
#pragma unroll
        for (int i = 0; i < 8; i++)
#pragma unroll
            for (int j = 0; j < 4; j++) S[i][j] = 0.f;

#pragma unroll
        for (int kb = 0; kb < 8; kb++) {
            uint32_t aqh[4], aql[4];
            const uint32_t arow = (uint32_t)(w * 16 + (mi & 1) * 8 + lr) * 272
                                + (uint32_t)(kb * 16 + (mi >> 1) * 8) * 2;
            ldsm_x4(aqh, sb + FQH + arow);
            ldsm_x4(aql, sb + FQL + arow);
#pragma unroll
            for (int nbp = 0; nbp < 4; nbp++) {
                const int kblk = tt * 64 + nbp * 16;
                if (kblk + 15 < wlo || kblk > whi) continue;
                uint32_t bkh[4], bkl[4];
                const uint32_t brow = (uint32_t)(nbp * 16 + (mi >> 1) * 8 + lr) * 272
                                    + (uint32_t)(kb * 16 + (mi & 1) * 8) * 2;
                ldsm_x4(bkh, sb + FKH + brow);
                ldsm_x4(bkl, sb + FKL + brow);
                mma_bf16(S[nbp * 2],     aqh, &bkh[0]);
                mma_bf16(S[nbp * 2 + 1], aqh, &bkh[2]);
                mma_bf16(S[nbp * 2],     aqh, &bkl[0]);
                mma_bf16(S[nbp * 2 + 1], aqh, &bkl[2]);
                mma_bf16(S[nbp * 2],     aql, &bkh[0]);
                mma_bf16(S[nbp * 2 + 1], aql, &bkh[2]);
            }
        }

        // ---- band mask + running softmax ----
        float mx0 = -1e30f, mx1 = -1e30f;
#pragma unroll
        for (int nb = 0; nb < 8; nb++) {
            const int jj = tt * 64 + nb * 8 + t4 * 2;
            if (jj < vlo0     || jj > vhi0)     S[nb][0] = -1e30f;
            if (jj + 1 < vlo0 || jj + 1 > vhi0) S[nb][1] = -1e30f;
            if (jj < vlo1     || jj > vhi1)     S[nb][2] = -1e30f;
            if (jj + 1 < vlo1 || jj + 1 > vhi1) S[nb][3] = -1e30f;
            mx0 = fmaxf(mx0, fmaxf(S[nb][0], S[nb][1]));
            mx1 = fmaxf(mx1, fmaxf(S[nb][2], S[nb][3]));
        }
        mx0 = fmaxf(mx0, __shfl_xor_sync(0xffffffffu, mx0, 1));
        mx0 = fmaxf(mx0, __shfl_xor_sync(0xffffffffu, mx0, 2));
        mx1 = fmaxf(mx1, __shfl_xor_sync(0xffffffffu, mx1, 1));
        mx1 = fmaxf(mx1, __shfl_xor_sync(0xffffffffu, mx1, 2));

        const float mn0 = fmaxf(m0, mx0);
        const float mn1 = fmaxf(m1, mx1);
        const float f0 = __expf(m0 - mn0);
        const float f1 = __expf(m1 - mn1);

        float sum0 = 0.f, sum1 = 0.f;
#pragma unroll
        for (int nb = 0; nb < 8; nb++) {
            float e0 = (S[nb][0] == -1e30f) ? 0.f : __expf(S[nb][0] - mn0);
            float e1 = (S[nb][1] == -1e30f) ? 0.f : __expf(S[nb][1] - mn0);
            float e2 = (S[nb][2] == -1e30f) ? 0.f : __expf(S[nb][2] - mn1);
            float e3 = (S[nb][3] == -1e30f) ? 0.f : __expf(S[nb][3] - mn1);
            S[nb][0] = e0; S[nb][1] = e1; S[nb][2] = e2; S[nb][3] = e3;
            sum0 += e0 + e1;
            sum1 += e2 + e3;
        }
        sum0 += __shfl_xor_sync(0xffffffffu, sum0, 1);
        sum0 += __shfl_xor_sync(0xffffffffu, sum0, 2);
        sum1 += __shfl_xor_sync(0xffffffffu, sum1, 1);
        sum1 += __shfl_xor_sync(0xffffffffu, sum1, 2);
        L0 = L0 * f0 + sum0;
        L1 = L1 * f1 + sum1;
        m0 = mn0; m1 = mn1;

#pragma unroll
        for (int nb = 0; nb < 16; nb++) {
            ctx[nb][0] *= f0; ctx[nb][1] *= f0;
            ctx[nb][2] *= f1; ctx[nb][3] *= f1;
        }

        // ---- PV (skip fully-masked 16-key blocks per warp) ----
#pragma unroll
        for (int kb2 = 0; kb2 < 4; kb2++) {
            const int kblk = tt * 64 + kb2 * 16;
            if (kblk + 15 < wlo || kblk > whi) continue;
            uint32_t ahi[4], alo[4];
            split2(S[2 * kb2][0],     S[2 * kb2][1],     ahi[0], alo[0]);
            split2(S[2 * kb2][2],     S[2 * kb2][3],     ahi[1], alo[1]);
            split2(S[2 * kb2 + 1][0], S[2 * kb2 + 1][1], ahi[2], alo[2]);
            split2(S[2 * kb2 + 1][2], S[2 * kb2 + 1][3], ahi[3], alo[3]);
#pragma unroll
            for (int dbp = 0; dbp < 8; dbp++) {
                uint32_t bvh[4], bvl[4];
                const uint32_t vrow = (uint32_t)(dbp * 16 + (mi >> 1) * 8 + lr) * 144
                                    + (uint32_t)(kb2 * 16 + (mi & 1) * 8) * 2;
                ldsm_x4(bvh, sb + FVH + vrow);
                ldsm_x4(bvl, sb + FVL + vrow);
                mma_bf16(ctx[dbp * 2],     ahi, &bvh[0]);
                mma_bf16(ctx[dbp * 2 + 1], ahi, &bvh[2]);
                mma_bf16(ctx[dbp * 2],     ahi, &bvl[0]);
                mma_bf16(ctx[dbp * 2 + 1], ahi, &bvl[2]);
                mma_bf16(ctx[dbp * 2],     alo, &bvh[0]);
                mma_bf16(ctx[dbp * 2 + 1], alo, &bvh[2]);
            }
        }
    }

    // ---- store ctx (tf32-rounded: feeds out_proj GEMM) ----
    const float inv0 = 1.f / L0;
    const float inv1 = 1.f / L1;
    const int ig0 = i0 + qi0;
    const int ig1 = i0 + qi1;
    if (ig0 < SS) {
        const size_t ro = (size_t)(b * SS + ig0) * DD + h * HDIM;
#pragma unroll
        for (int nb = 0; nb < 16; nb++) {
            const int d = nb * 8 + t4 * 2;
            *(float2*)(ctxp + ro + d) =
                make_float2(tf32r(ctx[nb][0] * inv0), tf32r(ctx[nb][1] * inv0));
        }
    }
    if (ig1 < SS) {
        const size_t ro = (size_t)(b * SS + ig1) * DD + h * HDIM;
#pragma unroll
        for (int nb = 0; nb < 16; nb++) {
            const int d = nb * 8 + t4 * 2;
            *(float2*)(ctxp + ro + d) =
                make_float2(tf32r(ctx[nb][2] * inv1), tf32r(ctx[nb][3] * inv1));
        }
    }
}

// ---------------- add + LN1: warp per row, 8 rows/block ---------------------
__global__ void __launch_bounds__(256)
add_ln_kernel(const float* __restrict__ x, const float* __restrict__ y,
              const float* __restrict__ w, const float* __restrict__ b,
              float* __restrict__ out)
{
    const int warp = threadIdx.x >> 5;
    const int lane = threadIdx.x & 31;
    const int row  = blockIdx.x * 8 + warp;
    const size_t base = (size_t)row * DD + lane * 8;

    float4 a0 = *(const float4*)(x + base);
    float4 a1 = *(const float4*)(x + base + 4);
    float4 c0 = *(const float4*)(y + base);
    float4 c1 = *(const float4*)(y + base + 4);
    float v[8] = { a0.x + c0.x, a0.y + c0.y, a0.z + c0.z, a0.w + c0.w,
                   a1.x + c1.x, a1.y + c1.y, a1.z + c1.z, a1.w + c1.w };

    float s = 0.f, q = 0.f;
#pragma unroll
    for (int e = 0; e < 8; e++) { s += v[e]; q += v[e] * v[e]; }
#pragma unroll
    for (int o = 16; o; o >>= 1) {
        s += __shfl_xor_sync(0xffffffffu, s, o);
        q += __shfl_xor_sync(0xffffffffu, q, o);
    }
    const float mean = s * (1.f / DD);
    const float var  = q * (1.f / DD) - mean * mean;
    const float inv  = rsqrtf(var + 1e-5f);

    float4 w0 = *(const float4*)(w + lane * 8);
    float4 w1 = *(const float4*)(w + lane * 8 + 4);
    float4 b0 = *(const float4*)(b + lane * 8);
    float4 b1 = *(const float4*)(b + lane * 8 + 4);
    const float ww[8] = { w0.x, w0.y, w0.z, w0.w, w1.x, w1.y, w1.z, w1.w };
    const float bb[8] = { b0.x, b0.y, b0.z, b0.w, b1.x, b1.y, b1.z, b1.w };

    float o0[8];
#pragma unroll
    for (int e = 0; e < 8; e++)
        o0[e] = tf32r((v[e] - mean) * inv * ww[e] + bb[e]);
    *(float4*)(out + base)     = make_float4(o0[0], o0[1], o0[2], o0[3]);
    *(float4*)(out + base + 4) = make_float4(o0[4], o0[5], o0[6], o0[7]);
}

// ---------------- fused add + LN2 + head: warp per row, 8 rows/block --------
__global__ void __launch_bounds__(256)
ln2_head_kernel(const float* __restrict__ x, const float* __restrict__ y,
                const float* __restrict__ w, const float* __restrict__ b,
                const float* __restrict__ wc, float* __restrict__ out)
{
    const int warp = threadIdx.x >> 5;
    const int lane = threadIdx.x & 31;
    const int row  = blockIdx.x * 8 + warp;
    const size_t base = (size_t)row * DD + lane * 8;

    float4 a0 = *(const float4*)(x + base);
    float4 a1 = *(const float4*)(x + base + 4);
    float4 c0 = *(const float4*)(y + base);
    float4 c1 = *(const float4*)(y + base + 4);
    float v[8] = { a0.x + c0.x, a0.y + c0.y, a0.z + c0.z, a0.w + c0.w,
                   a1.x + c1.x, a1.y + c1.y, a1.z + c1.z, a1.w + c1.w };

    float s = 0.f, q = 0.f;
#pragma unroll
    for (int e = 0; e < 8; e++) { s += v[e]; q += v[e] * v[e]; }
#pragma unroll
    for (int o = 16; o; o >>= 1) {
        s += __shfl_xor_sync(0xffffffffu, s, o);
        q += __shfl_xor_sync(0xffffffffu, q, o);
    }
    const float mean = s * (1.f / DD);
    const float var  = q * (1.f / DD) - mean * mean;
    const float inv  = rsqrtf(var + 1e-5f);

    float4 w0 = *(const float4*)(w + lane * 8);
    float4 w1 = *(const float4*)(w + lane * 8 + 4);
    float4 b0 = *(const float4*)(b + lane * 8);
    float4 b1 = *(const float4*)(b + lane * 8 + 4);
    float4 wc0 = *(const float4*)(wc + lane * 8);
    float4 wc1 = *(const float4*)(wc + lane * 8 + 4);
    const float ww[8]  = { w0.x, w0.y, w0.z, w0.w, w1.x, w1.y, w1.z, w1.w };
    const float bb[8]  = { b0.x, b0.y, b0.z, b0.w, b1.x, b1.y, b1.z, b1.w };
    const float wcc[8] = { wc0.x, wc0.y, wc0.z, wc0.w, wc1.x, wc1.y, wc1.z, wc1.w };

    float d = 0.f;
#pragma unroll
    for (int e = 0; e < 8; e++)
        d += ((v[e] - mean) * inv * ww[e] + bb[e]) * wcc[e];
#pragma unroll
    for (int o = 16; o; o >>= 1) d += __shfl_xor_sync(0xffffffffu, d, o);
    if (lane == 0) out[row] = d + wc[256];
}

// ---------------- host launch -----------------------------------------------
template<typename T>
static T* dptr(const void* sym) {
    void* p = nullptr;
    cudaGetSymbolAddress(&p, sym);
    return (T*)p;
}

extern "C" void kernel_launch(void* const* d_in, const int* in_sizes, int n_in,
                              void* d_out, int out_size)
{
    const float* src        = (const float*)d_in[0];
    const float* W_enc      = (const float*)d_in[2];
    const float* b_enc      = (const float*)d_in[3];
    const float* in_proj_w  = (const float*)d_in[4];
    const float* in_proj_b  = (const float*)d_in[5];
    const float* out_proj_w = (const float*)d_in[6];
    const float* out_proj_b = (const float*)d_in[7];
    const float* ln1_w      = (const float*)d_in[8];
    const float* ln1_b      = (const float*)d_in[9];
    const float* lin1_w     = (const float*)d_in[10];
    const float* lin1_b     = (const float*)d_in[11];
    const float* lin2_w     = (const float*)d_in[12];
    const float* lin2_b     = (const float*)d_in[13];
    const float* ln2_w      = (const float*)d_in[14];
    const float* ln2_b      = (const float*)d_in[15];
    const float* fc1_w      = (const float*)d_in[16];
    const float* fc1_b      = (const float*)d_in[17];
    const float* fc2_w      = (const float*)d_in[18];
    const float* fc2_b      = (const float*)d_in[19];
    float* out = (float*)d_out;

    float* x    = dptr<float>(g_x);
    float* ctx  = dptr<float>(g_ctx);
    float* att  = dptr<float>(g_att);
    float* h1   = dptr<float>(g_h1);
    float* ff   = dptr<float>(g_ff);
    float* ff2  = dptr<float>(g_ff2);
    float* wc   = dptr<float>(g_wc);
    float* pos  = dptr<float>(g_pos);
    float* w    = dptr<float>(g_w);
    __nv_bfloat16* qh  = dptr<__nv_bfloat16>(g_qh);
    __nv_bfloat16* ql  = dptr<__nv_bfloat16>(g_ql);
    __nv_bfloat16* kh  = dptr<__nv_bfloat16>(g_kh);
    __nv_bfloat16* kl  = dptr<__nv_bfloat16>(g_kl);
    __nv_bfloat16* vth = dptr<__nv_bfloat16>(g_vth);
    __nv_bfloat16* vtl = dptr<__nv_bfloat16>(g_vtl);

    cudaFuncSetAttribute(tf32_gemm<0>, cudaFuncAttributeMaxDynamicSharedMemorySize, TSM_TOTAL);
    cudaFuncSetAttribute(tf32_gemm<1>, cudaFuncAttributeMaxDynamicSharedMemorySize, TSM_TOTAL);
    cudaFuncSetAttribute(tf32_gemm<2>, cudaFuncAttributeMaxDynamicSharedMemorySize, TSM_TOTAL);
    cudaFuncSetAttribute(tf32_gemm<3>, cudaFuncAttributeMaxDynamicSharedMemorySize, TSM_TOTAL);
    cudaFuncSetAttribute(flash_attn_kernel, cudaFuncAttributeMaxDynamicSharedMemorySize, FSM_TOTAL);

    const dim3 blk(256);

    prep_all_kernel<<<(PN1 + PN3 + 255)/256, blk>>>(
        W_enc, in_proj_w, out_proj_w, lin1_w, lin2_w, w, pos);
    head_prep_kernel<<<16, blk>>>(fc1_w, fc1_b, fc2_w, fc2_b, wc);

    // 1. encoder projection + pos -> x
    tf32_gemm<1><<<dim3(MM/128, DD/128), blk, TSM_TOTAL>>>(
        src, w + WOFF_ENC, b_enc, pos, x, DD,
        nullptr, nullptr, nullptr, nullptr, nullptr, nullptr);
    // 2. qkv projection -> bf16 hi/lo q/k/vT
    tf32_gemm<3><<<dim3(MM/128, (3*DD)/128), blk, TSM_TOTAL>>>(
        x, w + WOFF_QKV, in_proj_b, nullptr, nullptr, 0,
        qh, ql, kh, kl, vth, vtl);
    // 3. flash banded attention -> ctx
    flash_attn_kernel<<<dim3(32, BB*HH), 128, FSM_TOTAL>>>(
        qh, ql, kh, kl, vth, vtl, ctx);
    // 4. output projection
    tf32_gemm<0><<<dim3(MM/128, DD/128), blk, TSM_TOTAL>>>(
        ctx, w + WOFF_OUT, out_proj_b, nullptr, att, DD,
        nullptr, nullptr, nullptr, nullptr, nullptr, nullptr);
    // 5. add + LN1 (warp per row)
    add_ln_kernel<<<MM/8, blk>>>(x, att, ln1_w, ln1_b, h1);
    // 6. ffn1 + relu
    tf32_gemm<2><<<dim3(MM/128, FFN/128), blk, TSM_TOTAL>>>(
        h1, w + WOFF_L1, lin1_b, nullptr, ff, FFN,
        nullptr, nullptr, nullptr, nullptr, nullptr, nullptr);
    // 7. ffn2
    tf32_gemm<0><<<dim3(MM/128, DD/128), blk, TSM_TOTAL>>>(
        ff, w + WOFF_L2, lin2_b, nullptr, ff2, DD,
        nullptr, nullptr, nullptr, nullptr, nullptr, nullptr);
    // 8. fused add + LN2 + head (warp per row) -> logits [B,S]
    ln2_head_kernel<<<MM/8, blk>>>(h1, ff2, ln2_w, ln2_b, wc, out);
}